// round 2
// baseline (speedup 1.0000x reference)
#include <cuda_runtime.h>
#include <cuda_bf16.h>
#include <math.h>

// ---------------- problem constants ----------------
#define N_NODES 8192
#define N_EDGES 2048
#define L_TOK   8
#define D_EMB   64
#define FD      512          // L_TOK * D_EMB
#define DG      256
#define NH      4
#define HD      64           // DG / NH
#define VOCAB   10000
#define NROWS   (N_EDGES * L_TOK)   // 16384 sequence rows

// ---------------- scratch (device globals; no allocation allowed) ----------------
__device__ float g_x  [N_NODES * FD];
__device__ float g_e  [N_EDGES * FD];
__device__ float g_msg[N_EDGES * FD];
__device__ float g_agg[N_NODES * FD];
__device__ float g_h  [N_NODES * FD];
__device__ float g_zin[NROWS * D_EMB];
__device__ float g_zg [NROWS * DG];
__device__ float g_q  [NROWS * DG];
__device__ float g_k  [NROWS * DG];
__device__ float g_v  [NROWS * DG];
__device__ float g_ao [NROWS * DG];
__device__ float g_x1 [NROWS * DG];
__device__ float g_ffn[NROWS * 4 * DG];
__device__ float g_x2 [NROWS * DG];
__device__ float g_y  [NROWS * D_EMB];
__device__ float g_rowmax[NROWS];
__device__ float g_rowinv[NROWS];
__device__ int   g_mtok[NROWS];

// ---------------- small kernels ----------------

// labels + masked tokens. mask word tested as raw-bits != 0 (covers int32 and fp32 bool encodings)
__global__ void k_labels(const int* __restrict__ etok, const int* __restrict__ maskbits,
                         float* __restrict__ labels_out)
{
    int t = blockIdx.x * blockDim.x + threadIdx.x;
    if (t >= NROWS) return;
    int e = t >> 3;
    int tok = etok[t];
    bool masked = (maskbits[e] != 0) && (tok > 3);   // SPECIAL = {0,1,2,3}
    if (labels_out) labels_out[t] = masked ? (float)tok : -100.0f;
    g_mtok[t] = masked ? 4 : tok;                     // MASK_ID = 4
}

// embedding gather -> flattened [rows, L*D]
__global__ void k_embed(const int* __restrict__ toks, const float* __restrict__ emb,
                        float* __restrict__ out, int total_f4)
{
    int i = blockIdx.x * blockDim.x + threadIdx.x;
    if (i >= total_f4) return;
    int slot = i >> 4;          // token slot (row*8 + l)
    int d4   = i & 15;
    int tok  = toks[slot];
    ((float4*)out)[i] = ((const float4*)emb)[tok * 16 + d4];
}

__global__ void k_zero(float* __restrict__ p, int total_f4)
{
    int i = blockIdx.x * blockDim.x + threadIdx.x;
    if (i < total_f4) ((float4*)p)[i] = make_float4(0.f, 0.f, 0.f, 0.f);
}

__global__ void k_scatter(const float* __restrict__ msg, const int* __restrict__ dst,
                          float* __restrict__ agg)
{
    int t = blockIdx.x * blockDim.x + threadIdx.x;
    if (t >= N_EDGES * FD) return;
    int e = t >> 9, c = t & 511;
    atomicAdd(&agg[dst[e] * FD + c], msg[t]);
}

// z_in[r, d] = h[src[e], l*64+d] + h[dst[e], l*64+d]   (r = e*8+l)
__global__ void k_zin(const float* __restrict__ h, const int* __restrict__ src,
                      const int* __restrict__ dst, float* __restrict__ zin)
{
    int i = blockIdx.x * blockDim.x + threadIdx.x;   // NROWS*16 float4s
    if (i >= NROWS * 16) return;
    int r = i >> 4, d4 = i & 15;
    int e = r >> 3, l = r & 7;
    const float4* h4 = (const float4*)h;
    float4 a = h4[src[e] * 128 + l * 16 + d4];
    float4 b = h4[dst[e] * 128 + l * 16 + d4];
    ((float4*)zin)[i] = make_float4(a.x + b.x, a.y + b.y, a.z + b.z, a.w + b.w);
}

// ---------------- generic tiled fp32 GEMM: C = act(A@B + bias + Add) ----------------
// BM=BN=64, BK=16, 256 threads, 4x4 micro-tile. Requires M%64==0, N%64==0, K%16==0.
// ACT: 0 none, 1 relu, 2 gelu(tanh). Add has row-stride N; optional row remap via addIdx.
template<int ACT, bool HAS_BIAS, bool HAS_ADD, bool ADD_IDX>
__global__ void __launch_bounds__(256)
gemm64(const float* __restrict__ A, const float* __restrict__ B,
       const float* __restrict__ bias, const float* __restrict__ Add,
       const int* __restrict__ addIdx, float* __restrict__ C,
       int M, int N, int K)
{
    __shared__ float As[16][65];
    __shared__ float Bs[16][64];
    int tid = threadIdx.x;
    int bx = blockIdx.x, by = blockIdx.y;
    int tx = tid & 15, ty = tid >> 4;
    int m0 = by * 64, n0 = bx * 64;

    float acc[4][4];
#pragma unroll
    for (int i = 0; i < 4; i++)
#pragma unroll
        for (int j = 0; j < 4; j++) acc[i][j] = 0.f;

    int ar = tid >> 2;            // 0..63   A tile row
    int akq = (tid & 3) * 4;      // k quad within tile
    int bk = tid >> 4;            // 0..15   B tile k row
    int bnq = (tid & 15) * 4;     // n quad

    for (int k0 = 0; k0 < K; k0 += 16) {
        float4 a = *(const float4*)(A + (size_t)(m0 + ar) * K + k0 + akq);
        As[akq + 0][ar] = a.x; As[akq + 1][ar] = a.y;
        As[akq + 2][ar] = a.z; As[akq + 3][ar] = a.w;
        float4 b = *(const float4*)(B + (size_t)(k0 + bk) * N + n0 + bnq);
        *(float4*)&Bs[bk][bnq] = b;
        __syncthreads();
#pragma unroll
        for (int kk = 0; kk < 16; kk++) {
            float av[4], bv[4];
#pragma unroll
            for (int i = 0; i < 4; i++) av[i] = As[kk][ty * 4 + i];
#pragma unroll
            for (int j = 0; j < 4; j++) bv[j] = Bs[kk][tx * 4 + j];
#pragma unroll
            for (int i = 0; i < 4; i++)
#pragma unroll
                for (int j = 0; j < 4; j++) acc[i][j] = fmaf(av[i], bv[j], acc[i][j]);
        }
        __syncthreads();
    }

#pragma unroll
    for (int i = 0; i < 4; i++) {
        int row = m0 + ty * 4 + i;
        int arow = row;
        if (HAS_ADD && ADD_IDX) arow = addIdx[row];
#pragma unroll
        for (int j = 0; j < 4; j++) {
            int col = n0 + tx * 4 + j;
            float v = acc[i][j];
            if (HAS_BIAS) v += bias[col];
            if (HAS_ADD)  v += Add[(size_t)arow * N + col];
            if (ACT == 1) v = fmaxf(v, 0.f);
            if (ACT == 2) {
                float t = 0.7978845608028654f * (v + 0.044715f * v * v * v);
                v = 0.5f * v * (1.f + tanhf(t));
            }
            C[(size_t)row * N + col] = v;
        }
    }
}

// ---------------- attention (B=2048 edges, S=8, NH=4, HD=64) ----------------
__global__ void __launch_bounds__(256)
k_attn(const float* __restrict__ Q, const float* __restrict__ Km,
       const float* __restrict__ V, float* __restrict__ O)
{
    int e = blockIdx.x;
    int tid = threadIdx.x;
    __shared__ float qs[8][DG], ks[8][DG], vs[8][DG];
    __shared__ float att[NH][8][8];

    for (int i = tid; i < 8 * DG; i += 256) {
        int s = i >> 8, c = i & 255;
        size_t base = (size_t)(e * 8 + s) * DG + c;
        qs[s][c] = Q[base]; ks[s][c] = Km[base]; vs[s][c] = V[base];
    }
    __syncthreads();
    {
        int h = tid >> 6, rem = tid & 63, qi = rem >> 3, ki = rem & 7;
        float acc = 0.f;
#pragma unroll
        for (int d = 0; d < HD; d++) acc = fmaf(qs[qi][h * HD + d], ks[ki][h * HD + d], acc);
        att[h][qi][ki] = acc * 0.125f;     // 1/sqrt(64)
    }
    __syncthreads();
    if (tid < 32) {
        int h = tid >> 3, qi = tid & 7;
        float m = -1e30f;
#pragma unroll
        for (int ki = 0; ki < 8; ki++) m = fmaxf(m, att[h][qi][ki]);
        float s = 0.f, ex[8];
#pragma unroll
        for (int ki = 0; ki < 8; ki++) { ex[ki] = __expf(att[h][qi][ki] - m); s += ex[ki]; }
        float inv = 1.f / s;
#pragma unroll
        for (int ki = 0; ki < 8; ki++) att[h][qi][ki] = ex[ki] * inv;
    }
    __syncthreads();
    {
        int c = tid, h = c >> 6;
#pragma unroll
        for (int s = 0; s < 8; s++) {
            float acc = 0.f;
#pragma unroll
            for (int ki = 0; ki < 8; ki++) acc = fmaf(att[h][s][ki], vs[ki][c], acc);
            O[(size_t)(e * 8 + s) * DG + c] = acc;
        }
    }
}

// ---------------- lm_head GEMM: logits = Y[16384,64] @ emb^T[64,10000] ----------------
// K=64 fits entirely in smem (no K loop). grid (157, 256). Handles vocab edge.
__global__ void __launch_bounds__(256)
lm_gemm(const float* __restrict__ Y, const float* __restrict__ emb,
        float* __restrict__ logits)
{
    __shared__ float As[64][65];
    __shared__ float Bs[64][65];
    int tid = threadIdx.x;
    int bx = blockIdx.x, by = blockIdx.y;
    int r0 = tid >> 4;
    int kc = (tid & 15) * 4;
#pragma unroll
    for (int rep = 0; rep < 4; rep++) {
        int r = r0 + rep * 16;
        float4 a = *(const float4*)(Y + (size_t)(by * 64 + r) * 64 + kc);
        As[kc + 0][r] = a.x; As[kc + 1][r] = a.y; As[kc + 2][r] = a.z; As[kc + 3][r] = a.w;
        int vr = bx * 64 + r;
        float4 b = (vr < VOCAB) ? *(const float4*)(emb + (size_t)vr * 64 + kc)
                                : make_float4(0.f, 0.f, 0.f, 0.f);
        Bs[kc + 0][r] = b.x; Bs[kc + 1][r] = b.y; Bs[kc + 2][r] = b.z; Bs[kc + 3][r] = b.w;
    }
    __syncthreads();
    int tx = tid & 15, ty = tid >> 4;
    float acc[4][4];
#pragma unroll
    for (int i = 0; i < 4; i++)
#pragma unroll
        for (int j = 0; j < 4; j++) acc[i][j] = 0.f;
#pragma unroll
    for (int kk = 0; kk < 64; kk++) {
        float av[4], bv[4];
#pragma unroll
        for (int i = 0; i < 4; i++) av[i] = As[kk][ty * 4 + i];
#pragma unroll
        for (int j = 0; j < 4; j++) bv[j] = Bs[kk][tx * 4 + j];
#pragma unroll
        for (int i = 0; i < 4; i++)
#pragma unroll
            for (int j = 0; j < 4; j++) acc[i][j] = fmaf(av[i], bv[j], acc[i][j]);
    }
    int v = bx * 64 + tx * 4;
    if (v < VOCAB) {
#pragma unroll
        for (int i = 0; i < 4; i++) {
            int row = by * 64 + ty * 4 + i;
            float4 w = make_float4(acc[i][0], acc[i][1], acc[i][2], acc[i][3]);
            *(float4*)(logits + (size_t)row * VOCAB + v) = w;
        }
    }
}

// ---------------- softmax: online stats then normalize (in place over logits) ----------------
__global__ void __launch_bounds__(256)
k_softmax_stats(const float* __restrict__ logits)
{
    int row = blockIdx.x, tid = threadIdx.x;
    const float4* p = (const float4*)(logits + (size_t)row * VOCAB);
    float m = -1e30f, s = 0.f;
    for (int i = tid; i < VOCAB / 4; i += 256) {
        float4 q = p[i];
        float xs[4] = {q.x, q.y, q.z, q.w};
#pragma unroll
        for (int c = 0; c < 4; c++) {
            float x = xs[c];
            if (x > m) { s = s * __expf(m - x) + 1.f; m = x; }
            else s += __expf(x - m);
        }
    }
    __shared__ float sm[256], ss[256];
    sm[tid] = m; ss[tid] = s;
    __syncthreads();
    for (int off = 128; off > 0; off >>= 1) {
        if (tid < off) {
            float m1 = sm[tid], s1 = ss[tid];
            float m2 = sm[tid + off], s2 = ss[tid + off];
            float M = fmaxf(m1, m2);
            sm[tid] = M;
            ss[tid] = s1 * __expf(m1 - M) + s2 * __expf(m2 - M);
        }
        __syncthreads();
    }
    if (tid == 0) { g_rowmax[row] = sm[0]; g_rowinv[row] = 1.f / ss[0]; }
}

__global__ void __launch_bounds__(256)
k_softmax_norm(float* __restrict__ probs)
{
    int row = blockIdx.x, tid = threadIdx.x;
    float m = g_rowmax[row], inv = g_rowinv[row];
    float4* p = (float4*)(probs + (size_t)row * VOCAB);
    for (int i = tid; i < VOCAB / 4; i += 256) {
        float4 q = p[i];
        q.x = __expf(q.x - m) * inv;
        q.y = __expf(q.y - m) * inv;
        q.z = __expf(q.z - m) * inv;
        q.w = __expf(q.w - m) * inv;
        p[i] = q;
    }
}

// ---------------- host launcher ----------------
extern "C" void kernel_launch(void* const* d_in, const int* in_sizes, int n_in,
                              void* d_out, int out_size)
{
    const int*   node_tokens = (const int*)d_in[0];
    const int*   edge_tokens = (const int*)d_in[1];
    const int*   edge_index  = (const int*)d_in[2];
    const int*   mask_rows   = (const int*)d_in[3];
    const float* emb   = (const float*)d_in[4];
    const float* W_msg = (const float*)d_in[5];
    const float* W_node= (const float*)d_in[6];
    const float* lc1_w = (const float*)d_in[7];
    const float* lc1_b = (const float*)d_in[8];
    const float* lc2_w = (const float*)d_in[9];
    const float* lc2_b = (const float*)d_in[10];
    const float* Wq  = (const float*)d_in[11];
    const float* Wk  = (const float*)d_in[12];
    const float* Wv  = (const float*)d_in[13];
    const float* Wo  = (const float*)d_in[14];
    const float* Wf1 = (const float*)d_in[15];
    const float* Wf2 = (const float*)d_in[16];
    const int* src = edge_index;
    const int* dst = edge_index + N_EDGES;

    // scratch addresses
    float *p_x, *p_e, *p_msg, *p_agg, *p_h, *p_zin, *p_zg, *p_q, *p_k, *p_v,
          *p_ao, *p_x1, *p_ffn, *p_x2, *p_y;
    int *p_mtok;
    cudaGetSymbolAddress((void**)&p_x,   g_x);
    cudaGetSymbolAddress((void**)&p_e,   g_e);
    cudaGetSymbolAddress((void**)&p_msg, g_msg);
    cudaGetSymbolAddress((void**)&p_agg, g_agg);
    cudaGetSymbolAddress((void**)&p_h,   g_h);
    cudaGetSymbolAddress((void**)&p_zin, g_zin);
    cudaGetSymbolAddress((void**)&p_zg,  g_zg);
    cudaGetSymbolAddress((void**)&p_q,   g_q);
    cudaGetSymbolAddress((void**)&p_k,   g_k);
    cudaGetSymbolAddress((void**)&p_v,   g_v);
    cudaGetSymbolAddress((void**)&p_ao,  g_ao);
    cudaGetSymbolAddress((void**)&p_x1,  g_x1);
    cudaGetSymbolAddress((void**)&p_ffn, g_ffn);
    cudaGetSymbolAddress((void**)&p_x2,  g_x2);
    cudaGetSymbolAddress((void**)&p_y,   g_y);
    cudaGetSymbolAddress((void**)&p_mtok, g_mtok);

    // output layout: probs-only, or labels(16384) ++ probs
    float* out = (float*)d_out;
    const long long PROBS_N = (long long)NROWS * VOCAB;
    float* labels_out = nullptr;
    float* probs = out;
    if ((long long)out_size >= PROBS_N + NROWS) { labels_out = out; probs = out + NROWS; }

    // 1) masking + embeddings
    k_labels<<<NROWS / 256, 256>>>(edge_tokens, mask_rows, labels_out);
    k_embed<<<(N_NODES * L_TOK * 16) / 256, 256>>>(node_tokens, emb, p_x, N_NODES * L_TOK * 16);
    k_embed<<<(N_EDGES * L_TOK * 16) / 256, 256>>>(p_mtok, emb, p_e, N_EDGES * L_TOK * 16);
    k_zero<<<(N_NODES * FD / 4) / 256, 256>>>(p_agg, N_NODES * FD / 4);

    // 2) GNN: msg = relu(e @ W_msg + x[src]); agg = scatter_add(msg, dst); h = relu(x @ W_node + agg)
    gemm64<1, false, true, true><<<dim3(FD / 64, N_EDGES / 64), 256>>>(
        p_e, W_msg, nullptr, p_x, src, p_msg, N_EDGES, FD, FD);
    k_scatter<<<(N_EDGES * FD) / 256, 256>>>(p_msg, dst, p_agg);
    gemm64<1, false, true, false><<<dim3(FD / 64, N_NODES / 64), 256>>>(
        p_x, W_node, nullptr, p_agg, nullptr, p_h, N_NODES, FD, FD);

    // 3) eh gather + lc1
    k_zin<<<(NROWS * 16) / 256, 256>>>(p_h, src, dst, p_zin);
    gemm64<0, true, false, false><<<dim3(DG / 64, NROWS / 64), 256>>>(
        p_zin, lc1_w, lc1_b, nullptr, nullptr, p_zg, NROWS, DG, D_EMB);

    // 4) transformer block
    gemm64<0, false, false, false><<<dim3(DG / 64, NROWS / 64), 256>>>(
        p_zg, Wq, nullptr, nullptr, nullptr, p_q, NROWS, DG, DG);
    gemm64<0, false, false, false><<<dim3(DG / 64, NROWS / 64), 256>>>(
        p_zg, Wk, nullptr, nullptr, nullptr, p_k, NROWS, DG, DG);
    gemm64<0, false, false, false><<<dim3(DG / 64, NROWS / 64), 256>>>(
        p_zg, Wv, nullptr, nullptr, nullptr, p_v, NROWS, DG, DG);
    k_attn<<<N_EDGES, 256>>>(p_q, p_k, p_v, p_ao);
    gemm64<0, false, true, false><<<dim3(DG / 64, NROWS / 64), 256>>>(
        p_ao, Wo, nullptr, p_zg, nullptr, p_x1, NROWS, DG, DG);
    gemm64<2, false, false, false><<<dim3(4 * DG / 64, NROWS / 64), 256>>>(
        p_x1, Wf1, nullptr, nullptr, nullptr, p_ffn, NROWS, 4 * DG, DG);
    gemm64<0, false, true, false><<<dim3(DG / 64, NROWS / 64), 256>>>(
        p_ffn, Wf2, nullptr, p_x1, nullptr, p_x2, NROWS, DG, 4 * DG);

    // 5) lc2
    gemm64<0, true, false, false><<<dim3(D_EMB / 64, NROWS / 64), 256>>>(
        p_x2, lc2_w, lc2_b, nullptr, nullptr, p_y, NROWS, D_EMB, DG);

    // 6) tied lm head + softmax (logits written into probs region, normalized in place)
    lm_gemm<<<dim3((VOCAB + 63) / 64, NROWS / 64), 256>>>(p_y, emb, probs);
    k_softmax_stats<<<NROWS, 256>>>(probs);
    k_softmax_norm<<<NROWS, 256>>>(probs);
}

// round 3
// speedup vs baseline: 1.6165x; 1.6165x over previous
#include <cuda_runtime.h>
#include <cuda_bf16.h>
#include <math.h>
#include <stdint.h>

// ---------------- problem constants ----------------
#define N_NODES 8192
#define N_EDGES 2048
#define L_TOK   8
#define D_EMB   64
#define FD      512          // L_TOK * D_EMB
#define DG      256
#define NH      4
#define HD      64           // DG / NH
#define VOCAB   10000
#define NROWS   (N_EDGES * L_TOK)   // 16384 sequence rows

// ---------------- scratch (device globals; no allocation allowed) ----------------
__device__ float g_x  [N_NODES * FD];
__device__ float g_e  [N_EDGES * FD];
__device__ float g_msg[N_EDGES * FD];
__device__ float g_agg[N_NODES * FD];
__device__ float g_h  [N_NODES * FD];
__device__ float g_zin[NROWS * D_EMB];
__device__ float g_zg [NROWS * DG];
__device__ float g_q  [NROWS * DG];
__device__ float g_k  [NROWS * DG];
__device__ float g_v  [NROWS * DG];
__device__ float g_ao [NROWS * DG];
__device__ float g_x1 [NROWS * DG];
__device__ float g_ffn[NROWS * 4 * DG];
__device__ float g_x2 [NROWS * DG];
__device__ float g_y  [NROWS * D_EMB];
__device__ int   g_mtok[NROWS];

// ---------------- helpers ----------------
__device__ __forceinline__ void split_tf32(float x, uint32_t& hi, uint32_t& lo) {
    uint32_t h;
    asm("cvt.rna.tf32.f32 %0, %1;" : "=r"(h) : "f"(x));
    float r = x - __uint_as_float(h);
    uint32_t l;
    asm("cvt.rna.tf32.f32 %0, %1;" : "=r"(l) : "f"(r));
    hi = h; lo = l;
}

__device__ __forceinline__ void mma8(float* c,
    uint32_t a0, uint32_t a1, uint32_t a2, uint32_t a3,
    uint32_t b0, uint32_t b1)
{
    asm volatile(
        "mma.sync.aligned.m16n8k8.row.col.f32.tf32.tf32.f32 "
        "{%0,%1,%2,%3},{%4,%5,%6,%7},{%8,%9},{%0,%1,%2,%3};"
        : "+f"(c[0]), "+f"(c[1]), "+f"(c[2]), "+f"(c[3])
        : "r"(a0), "r"(a1), "r"(a2), "r"(a3), "r"(b0), "r"(b1));
}

__device__ __forceinline__ float gelu_f(float v) {
    float u = 0.7978845608028654f * (v + 0.044715f * v * v * v);
    float t;
    asm("tanh.approx.f32 %0, %1;" : "=f"(t) : "f"(u));
    return 0.5f * v * (1.f + t);
}

// ---------------- small kernels ----------------
__global__ void k_labels(const int* __restrict__ etok, const int* __restrict__ maskbits,
                         float* __restrict__ labels_out)
{
    int t = blockIdx.x * blockDim.x + threadIdx.x;
    if (t >= NROWS) return;
    int e = t >> 3;
    int tok = etok[t];
    bool masked = (maskbits[e] != 0) && (tok > 3);   // SPECIAL = {0,1,2,3}
    if (labels_out) labels_out[t] = masked ? (float)tok : -100.0f;
    g_mtok[t] = masked ? 4 : tok;                     // MASK_ID = 4
}

__global__ void k_embed(const int* __restrict__ toks, const float* __restrict__ emb,
                        float* __restrict__ out, int total_f4)
{
    int i = blockIdx.x * blockDim.x + threadIdx.x;
    if (i >= total_f4) return;
    int slot = i >> 4;
    int d4   = i & 15;
    int tok  = toks[slot];
    ((float4*)out)[i] = ((const float4*)emb)[tok * 16 + d4];
}

__global__ void k_zero(float* __restrict__ p, int total_f4)
{
    int i = blockIdx.x * blockDim.x + threadIdx.x;
    if (i < total_f4) ((float4*)p)[i] = make_float4(0.f, 0.f, 0.f, 0.f);
}

__global__ void k_scatter(const float* __restrict__ msg, const int* __restrict__ dst,
                          float* __restrict__ agg)
{
    int t = blockIdx.x * blockDim.x + threadIdx.x;
    if (t >= N_EDGES * FD) return;
    int e = t >> 9, c = t & 511;
    atomicAdd(&agg[dst[e] * FD + c], msg[t]);
}

__global__ void k_zin(const float* __restrict__ h, const int* __restrict__ src,
                      const int* __restrict__ dst, float* __restrict__ zin)
{
    int i = blockIdx.x * blockDim.x + threadIdx.x;
    if (i >= NROWS * 16) return;
    int r = i >> 4, d4 = i & 15;
    int e = r >> 3, l = r & 7;
    const float4* h4 = (const float4*)h;
    float4 a = h4[src[e] * 128 + l * 16 + d4];
    float4 b = h4[dst[e] * 128 + l * 16 + d4];
    ((float4*)zin)[i] = make_float4(a.x + b.x, a.y + b.y, a.z + b.z, a.w + b.w);
}

// ---------------- tensor-core tf32(3x) GEMM ----------------
// C[M,N] = act(A[M,K] @ B + bias + Add).   B is [K,N] row-major, or (B_NMAJOR)
// a [N,K] row-major matrix used transposed (lm_head: emb).
// BM=128 fixed (M%128==0 required), BN in {64,128}, BK=16, 256 threads.
// 8 warps in 2(M)x4(N) grid; warp tile 64 x (BN/4).
// smem slots: uint4 {hi(k),lo(k),hi(k+4),lo(k+4)} at [(s*4+t)*DIM + rowcol].
template<int BN, int ACT, bool HAS_BIAS, bool HAS_ADD, bool ADD_IDX, bool B_NMAJOR, bool N_PRED>
__global__ void __launch_bounds__(256)
tgemm(const float* __restrict__ A, const float* __restrict__ B,
      const float* __restrict__ bias, const float* __restrict__ Add,
      const int* __restrict__ addIdx, float* __restrict__ C,
      int M, int N, int K)
{
    constexpr int BM = 128;
    constexpr int WN = BN / 4;
    constexpr int MT = 4;          // 64/16
    constexpr int NT = WN / 8;

    __shared__ uint4 As[8 * BM];
    __shared__ uint4 Bs[8 * BN];

    int tid = threadIdx.x;
    int lane = tid & 31, w = tid >> 5;
    int g = lane >> 2, tg = lane & 3;
    int wM = w >> 2, wN = w & 3;
    int m0 = blockIdx.y * BM, n0 = blockIdx.x * BN;

    float acc[MT][NT][4];
#pragma unroll
    for (int mt = 0; mt < MT; mt++)
#pragma unroll
        for (int nt = 0; nt < NT; nt++)
#pragma unroll
            for (int c = 0; c < 4; c++) acc[mt][nt][c] = 0.f;

    for (int k0 = 0; k0 < K; k0 += 16) {
        if (k0) __syncthreads();
        // ---- load + split A tile (128 x 16) ----
        {
            int m = tid >> 1, sh = tid & 1;
            const float* src = A + (size_t)(m0 + m) * K + k0 + 8 * sh;
            float4 f1 = *(const float4*)src;
            float4 f2 = *(const float4*)(src + 4);
            float c1[4] = {f1.x, f1.y, f1.z, f1.w};
            float c2[4] = {f2.x, f2.y, f2.z, f2.w};
#pragma unroll
            for (int t = 0; t < 4; t++) {
                uint4 q;
                split_tf32(c1[t], q.x, q.y);
                split_tf32(c2[t], q.z, q.w);
                As[(sh * 4 + t) * BM + m] = q;
            }
        }
        // ---- load + split B tile (16 x BN) ----
        for (int i = tid; i < 2 * BN; i += 256) {
            int n = i % BN, sh = i / BN;
            float c1[4], c2[4];
            if (B_NMAJOR) {
                if (!N_PRED || (n0 + n) < N) {
                    const float* src = B + (size_t)(n0 + n) * K + k0 + 8 * sh;
                    float4 f1 = *(const float4*)src;
                    float4 f2 = *(const float4*)(src + 4);
                    c1[0] = f1.x; c1[1] = f1.y; c1[2] = f1.z; c1[3] = f1.w;
                    c2[0] = f2.x; c2[1] = f2.y; c2[2] = f2.z; c2[3] = f2.w;
                } else {
#pragma unroll
                    for (int t = 0; t < 4; t++) { c1[t] = 0.f; c2[t] = 0.f; }
                }
            } else {
#pragma unroll
                for (int t = 0; t < 4; t++) {
                    c1[t] = B[(size_t)(k0 + 8 * sh + t) * N + n0 + n];
                    c2[t] = B[(size_t)(k0 + 8 * sh + 4 + t) * N + n0 + n];
                }
            }
#pragma unroll
            for (int t = 0; t < 4; t++) {
                uint4 q;
                split_tf32(c1[t], q.x, q.y);
                split_tf32(c2[t], q.z, q.w);
                Bs[(sh * 4 + t) * BN + n] = q;
            }
        }
        __syncthreads();
        // ---- mma over 2 k-steps of 8 ----
#pragma unroll
        for (int s = 0; s < 2; s++) {
            uint4 af[MT][2];
#pragma unroll
            for (int mt = 0; mt < MT; mt++) {
                int mr = wM * 64 + mt * 16 + g;
                af[mt][0] = As[(s * 4 + tg) * BM + mr];
                af[mt][1] = As[(s * 4 + tg) * BM + mr + 8];
            }
            uint4 bf[NT];
#pragma unroll
            for (int nt = 0; nt < NT; nt++) {
                int nc = wN * WN + nt * 8 + g;
                bf[nt] = Bs[(s * 4 + tg) * BN + nc];
            }
#pragma unroll
            for (int mt = 0; mt < MT; mt++)
#pragma unroll
                for (int nt = 0; nt < NT; nt++) {
                    // Ah x Bh
                    mma8(acc[mt][nt], af[mt][0].x, af[mt][1].x, af[mt][0].z, af[mt][1].z,
                         bf[nt].x, bf[nt].z);
                    // Ah x Bl
                    mma8(acc[mt][nt], af[mt][0].x, af[mt][1].x, af[mt][0].z, af[mt][1].z,
                         bf[nt].y, bf[nt].w);
                    // Al x Bh
                    mma8(acc[mt][nt], af[mt][0].y, af[mt][1].y, af[mt][0].w, af[mt][1].w,
                         bf[nt].x, bf[nt].z);
                }
        }
    }

    // ---- epilogue ----
#pragma unroll
    for (int mt = 0; mt < MT; mt++) {
        int r1 = m0 + wM * 64 + mt * 16 + g;
        int r2 = r1 + 8;
        int a1 = r1, a2 = r2;
        if (HAS_ADD && ADD_IDX) { a1 = addIdx[r1]; a2 = addIdx[r2]; }
#pragma unroll
        for (int nt = 0; nt < NT; nt++) {
            int cb = n0 + wN * WN + nt * 8 + 2 * tg;
            if (N_PRED && cb >= N) continue;
            float e0 = acc[mt][nt][0], e1 = acc[mt][nt][1];
            float e2 = acc[mt][nt][2], e3 = acc[mt][nt][3];
            if (HAS_BIAS) { float b0 = bias[cb], b1 = bias[cb + 1]; e0 += b0; e1 += b1; e2 += b0; e3 += b1; }
            if (HAS_ADD) {
                e0 += Add[(size_t)a1 * N + cb]; e1 += Add[(size_t)a1 * N + cb + 1];
                e2 += Add[(size_t)a2 * N + cb]; e3 += Add[(size_t)a2 * N + cb + 1];
            }
            if (ACT == 1) { e0 = fmaxf(e0, 0.f); e1 = fmaxf(e1, 0.f); e2 = fmaxf(e2, 0.f); e3 = fmaxf(e3, 0.f); }
            if (ACT == 2) { e0 = gelu_f(e0); e1 = gelu_f(e1); e2 = gelu_f(e2); e3 = gelu_f(e3); }
            *(float2*)(C + (size_t)r1 * N + cb) = make_float2(e0, e1);
            *(float2*)(C + (size_t)r2 * N + cb) = make_float2(e2, e3);
        }
    }
}

// ---------------- attention (B=2048 edges, S=8, NH=4, HD=64) ----------------
__global__ void __launch_bounds__(256)
k_attn(const float* __restrict__ Q, const float* __restrict__ Km,
       const float* __restrict__ V, float* __restrict__ O)
{
    int e = blockIdx.x;
    int tid = threadIdx.x;
    __shared__ float qs[8][DG], ks[8][DG], vs[8][DG];
    __shared__ float att[NH][8][8];

    for (int i = tid; i < 8 * DG; i += 256) {
        int s = i >> 8, c = i & 255;
        size_t base = (size_t)(e * 8 + s) * DG + c;
        qs[s][c] = Q[base]; ks[s][c] = Km[base]; vs[s][c] = V[base];
    }
    __syncthreads();
    {
        int h = tid >> 6, rem = tid & 63, qi = rem >> 3, ki = rem & 7;
        float acc = 0.f;
#pragma unroll
        for (int d = 0; d < HD; d++) acc = fmaf(qs[qi][h * HD + d], ks[ki][h * HD + d], acc);
        att[h][qi][ki] = acc * 0.125f;
    }
    __syncthreads();
    if (tid < 32) {
        int h = tid >> 3, qi = tid & 7;
        float m = -1e30f;
#pragma unroll
        for (int ki = 0; ki < 8; ki++) m = fmaxf(m, att[h][qi][ki]);
        float s = 0.f, ex[8];
#pragma unroll
        for (int ki = 0; ki < 8; ki++) { ex[ki] = __expf(att[h][qi][ki] - m); s += ex[ki]; }
        float inv = 1.f / s;
#pragma unroll
        for (int ki = 0; ki < 8; ki++) att[h][qi][ki] = ex[ki] * inv;
    }
    __syncthreads();
    {
        int c = tid, h = c >> 6;
#pragma unroll
        for (int s = 0; s < 8; s++) {
            float acc = 0.f;
#pragma unroll
            for (int ki = 0; ki < 8; ki++) acc = fmaf(att[h][s][ki], vs[ki][c], acc);
            O[(size_t)(e * 8 + s) * DG + c] = acc;
        }
    }
}

// ---------------- fused softmax (stats + normalize, in place, row in registers) ----------------
__global__ void __launch_bounds__(256)
k_statsnorm(float* __restrict__ probs)
{
    int row = blockIdx.x, tid = threadIdx.x;
    const int NF4 = VOCAB / 4;   // 2500
    float4* p = (float4*)(probs + (size_t)row * VOCAB);

    float4 buf[10];
    float m = -1e30f, s = 0.f;
#pragma unroll
    for (int r = 0; r < 10; r++) {
        int i = tid + r * 256;
        if (i < NF4) {
            float4 q = p[i];
            buf[r] = q;
            float xs[4] = {q.x, q.y, q.z, q.w};
#pragma unroll
            for (int c = 0; c < 4; c++) {
                float x = xs[c];
                if (x > m) { s = s * __expf(m - x) + 1.f; m = x; }
                else s += __expf(x - m);
            }
        }
    }
    __shared__ float sm[256], ss[256];
    sm[tid] = m; ss[tid] = s;
    __syncthreads();
    for (int off = 128; off > 0; off >>= 1) {
        if (tid < off) {
            float m1 = sm[tid], s1 = ss[tid];
            float m2 = sm[tid + off], s2 = ss[tid + off];
            float M = fmaxf(m1, m2);
            sm[tid] = M;
            ss[tid] = s1 * __expf(m1 - M) + s2 * __expf(m2 - M);
        }
        __syncthreads();
    }
    float M = sm[0], inv = 1.f / ss[0];
#pragma unroll
    for (int r = 0; r < 10; r++) {
        int i = tid + r * 256;
        if (i < NF4) {
            float4 q = buf[r];
            q.x = __expf(q.x - M) * inv;
            q.y = __expf(q.y - M) * inv;
            q.z = __expf(q.z - M) * inv;
            q.w = __expf(q.w - M) * inv;
            p[i] = q;
        }
    }
}

// ---------------- host launcher ----------------
extern "C" void kernel_launch(void* const* d_in, const int* in_sizes, int n_in,
                              void* d_out, int out_size)
{
    const int*   node_tokens = (const int*)d_in[0];
    const int*   edge_tokens = (const int*)d_in[1];
    const int*   edge_index  = (const int*)d_in[2];
    const int*   mask_rows   = (const int*)d_in[3];
    const float* emb   = (const float*)d_in[4];
    const float* W_msg = (const float*)d_in[5];
    const float* W_node= (const float*)d_in[6];
    const float* lc1_w = (const float*)d_in[7];
    const float* lc1_b = (const float*)d_in[8];
    const float* lc2_w = (const float*)d_in[9];
    const float* lc2_b = (const float*)d_in[10];
    const float* Wq  = (const float*)d_in[11];
    const float* Wk  = (const float*)d_in[12];
    const float* Wv  = (const float*)d_in[13];
    const float* Wo  = (const float*)d_in[14];
    const float* Wf1 = (const float*)d_in[15];
    const float* Wf2 = (const float*)d_in[16];
    const int* src = edge_index;
    const int* dst = edge_index + N_EDGES;

    float *p_x, *p_e, *p_msg, *p_agg, *p_h, *p_zin, *p_zg, *p_q, *p_k, *p_v,
          *p_ao, *p_x1, *p_ffn, *p_x2, *p_y;
    int *p_mtok;
    cudaGetSymbolAddress((void**)&p_x,   g_x);
    cudaGetSymbolAddress((void**)&p_e,   g_e);
    cudaGetSymbolAddress((void**)&p_msg, g_msg);
    cudaGetSymbolAddress((void**)&p_agg, g_agg);
    cudaGetSymbolAddress((void**)&p_h,   g_h);
    cudaGetSymbolAddress((void**)&p_zin, g_zin);
    cudaGetSymbolAddress((void**)&p_zg,  g_zg);
    cudaGetSymbolAddress((void**)&p_q,   g_q);
    cudaGetSymbolAddress((void**)&p_k,   g_k);
    cudaGetSymbolAddress((void**)&p_v,   g_v);
    cudaGetSymbolAddress((void**)&p_ao,  g_ao);
    cudaGetSymbolAddress((void**)&p_x1,  g_x1);
    cudaGetSymbolAddress((void**)&p_ffn, g_ffn);
    cudaGetSymbolAddress((void**)&p_x2,  g_x2);
    cudaGetSymbolAddress((void**)&p_y,   g_y);
    cudaGetSymbolAddress((void**)&p_mtok, g_mtok);

    // output layout: probs-only, or labels(16384) ++ probs
    float* out = (float*)d_out;
    const long long PROBS_N = (long long)NROWS * VOCAB;
    float* labels_out = nullptr;
    float* probs = out;
    if ((long long)out_size >= PROBS_N + NROWS) { labels_out = out; probs = out + NROWS; }

    // 1) masking + embeddings
    k_labels<<<NROWS / 256, 256>>>(edge_tokens, mask_rows, labels_out);
    k_embed<<<(N_NODES * L_TOK * 16) / 256, 256>>>(node_tokens, emb, p_x, N_NODES * L_TOK * 16);
    k_embed<<<(N_EDGES * L_TOK * 16) / 256, 256>>>(p_mtok, emb, p_e, N_EDGES * L_TOK * 16);
    k_zero<<<(N_NODES * FD / 4) / 256, 256>>>(p_agg, N_NODES * FD / 4);

    // 2) GNN
    tgemm<128, 1, false, true, true, false, false><<<dim3(FD / 128, N_EDGES / 128), 256>>>(
        p_e, W_msg, nullptr, p_x, src, p_msg, N_EDGES, FD, FD);
    k_scatter<<<(N_EDGES * FD) / 256, 256>>>(p_msg, dst, p_agg);
    tgemm<128, 1, false, true, false, false, false><<<dim3(FD / 128, N_NODES / 128), 256>>>(
        p_x, W_node, nullptr, p_agg, nullptr, p_h, N_NODES, FD, FD);

    // 3) eh gather + lc1
    k_zin<<<(NROWS * 16) / 256, 256>>>(p_h, src, dst, p_zin);
    tgemm<128, 0, true, false, false, false, false><<<dim3(DG / 128, NROWS / 128), 256>>>(
        p_zin, lc1_w, lc1_b, nullptr, nullptr, p_zg, NROWS, DG, D_EMB);

    // 4) transformer block
    tgemm<128, 0, false, false, false, false, false><<<dim3(DG / 128, NROWS / 128), 256>>>(
        p_zg, Wq, nullptr, nullptr, nullptr, p_q, NROWS, DG, DG);
    tgemm<128, 0, false, false, false, false, false><<<dim3(DG / 128, NROWS / 128), 256>>>(
        p_zg, Wk, nullptr, nullptr, nullptr, p_k, NROWS, DG, DG);
    tgemm<128, 0, false, false, false, false, false><<<dim3(DG / 128, NROWS / 128), 256>>>(
        p_zg, Wv, nullptr, nullptr, nullptr, p_v, NROWS, DG, DG);
    k_attn<<<N_EDGES, 256>>>(p_q, p_k, p_v, p_ao);
    tgemm<128, 0, false, true, false, false, false><<<dim3(DG / 128, NROWS / 128), 256>>>(
        p_ao, Wo, nullptr, p_zg, nullptr, p_x1, NROWS, DG, DG);
    tgemm<128, 2, false, false, false, false, false><<<dim3(4 * DG / 128, NROWS / 128), 256>>>(
        p_x1, Wf1, nullptr, nullptr, nullptr, p_ffn, NROWS, 4 * DG, DG);
    tgemm<128, 0, false, true, false, false, false><<<dim3(DG / 128, NROWS / 128), 256>>>(
        p_ffn, Wf2, nullptr, p_x1, nullptr, p_x2, NROWS, DG, 4 * DG);

    // 5) lc2 (N=64 tile)
    tgemm<64, 0, true, false, false, false, false><<<dim3(1, NROWS / 128), 256>>>(
        p_x2, lc2_w, lc2_b, nullptr, nullptr, p_y, NROWS, D_EMB, DG);

    // 6) tied lm head (B = emb used N-major) + fused softmax
    tgemm<128, 0, false, false, false, true, true><<<dim3((VOCAB + 127) / 128, NROWS / 128), 256>>>(
        p_y, emb, nullptr, nullptr, nullptr, probs, NROWS, VOCAB, D_EMB);
    k_statsnorm<<<NROWS, 256>>>(probs);
}

// round 4
// speedup vs baseline: 1.6789x; 1.0386x over previous
#include <cuda_runtime.h>
#include <cuda_bf16.h>
#include <math.h>
#include <stdint.h>

// ---------------- problem constants ----------------
#define N_NODES 8192
#define N_EDGES 2048
#define L_TOK   8
#define D_EMB   64
#define FD      512          // L_TOK * D_EMB
#define DG      256
#define NH      4
#define HD      64
#define VOCAB   10000
#define NROWS   (N_EDGES * L_TOK)   // 16384

// ---------------- scratch ----------------
__device__ float g_x  [N_NODES * FD];
__device__ float g_e  [N_EDGES * FD];
__device__ float g_msg[N_EDGES * FD];
__device__ float g_agg[N_NODES * FD];
__device__ float g_h  [N_NODES * FD];
__device__ float g_zin[NROWS * D_EMB];
__device__ float g_zg [NROWS * DG];
__device__ float g_q  [NROWS * DG];
__device__ float g_k  [NROWS * DG];
__device__ float g_v  [NROWS * DG];
__device__ float g_ao [NROWS * DG];
__device__ float g_x1 [NROWS * DG];
__device__ float g_ffn[NROWS * 4 * DG];
__device__ float g_x2 [NROWS * DG];
__device__ float g_y  [NROWS * D_EMB];
__device__ int   g_mtok[NROWS];

// ---------------- helpers ----------------
__device__ __forceinline__ void splitpair(float x0, float x1, uint32_t& hi, uint32_t& lo) {
    __nv_bfloat162 h = __floats2bfloat162_rn(x0, x1);
    float h0 = __bfloat162float(h.x), h1 = __bfloat162float(h.y);
    __nv_bfloat162 l = __floats2bfloat162_rn(x0 - h0, x1 - h1);
    hi = *reinterpret_cast<uint32_t*>(&h);
    lo = *reinterpret_cast<uint32_t*>(&l);
}

__device__ __forceinline__ void mma16(float* c,
    uint32_t a0, uint32_t a1, uint32_t a2, uint32_t a3, uint32_t b0, uint32_t b1)
{
    asm volatile(
        "mma.sync.aligned.m16n8k16.row.col.f32.bf16.bf16.f32 "
        "{%0,%1,%2,%3},{%4,%5,%6,%7},{%8,%9},{%0,%1,%2,%3};"
        : "+f"(c[0]), "+f"(c[1]), "+f"(c[2]), "+f"(c[3])
        : "r"(a0), "r"(a1), "r"(a2), "r"(a3), "r"(b0), "r"(b1));
}

__device__ __forceinline__ float gelu_f(float v) {
    float u = 0.7978845608028654f * (v + 0.044715f * v * v * v);
    float t;
    asm("tanh.approx.f32 %0, %1;" : "=f"(t) : "f"(u));
    return 0.5f * v * (1.f + t);
}

__device__ __forceinline__ void upd_stats(float& m, float& s, float x) {
    if (x > m) { s = s * __expf(m - x) + 1.f; m = x; }
    else       { s += __expf(x - m); }
}

// ---------------- small kernels ----------------
__global__ void k_labels(const int* __restrict__ etok, const int* __restrict__ maskbits,
                         float* __restrict__ labels_out)
{
    int t = blockIdx.x * blockDim.x + threadIdx.x;
    if (t >= NROWS) return;
    int e = t >> 3;
    int tok = etok[t];
    bool masked = (maskbits[e] != 0) && (tok > 3);
    if (labels_out) labels_out[t] = masked ? (float)tok : -100.0f;
    g_mtok[t] = masked ? 4 : tok;
}

__global__ void k_embed(const int* __restrict__ toks, const float* __restrict__ emb,
                        float* __restrict__ out, int total_f4)
{
    int i = blockIdx.x * blockDim.x + threadIdx.x;
    if (i >= total_f4) return;
    int slot = i >> 4, d4 = i & 15;
    int tok = toks[slot];
    ((float4*)out)[i] = ((const float4*)emb)[tok * 16 + d4];
}

__global__ void k_zero(float* __restrict__ p, int total_f4)
{
    int i = blockIdx.x * blockDim.x + threadIdx.x;
    if (i < total_f4) ((float4*)p)[i] = make_float4(0.f, 0.f, 0.f, 0.f);
}

__global__ void k_scatter(const float* __restrict__ msg, const int* __restrict__ dst,
                          float* __restrict__ agg)
{
    int t = blockIdx.x * blockDim.x + threadIdx.x;
    if (t >= N_EDGES * FD) return;
    int e = t >> 9, c = t & 511;
    atomicAdd(&agg[dst[e] * FD + c], msg[t]);
}

__global__ void k_zin(const float* __restrict__ h, const int* __restrict__ src,
                      const int* __restrict__ dst, float* __restrict__ zin)
{
    int i = blockIdx.x * blockDim.x + threadIdx.x;
    if (i >= NROWS * 16) return;
    int r = i >> 4, d4 = i & 15;
    int e = r >> 3, l = r & 7;
    const float4* h4 = (const float4*)h;
    float4 a = h4[src[e] * 128 + l * 16 + d4];
    float4 b = h4[dst[e] * 128 + l * 16 + d4];
    ((float4*)zin)[i] = make_float4(a.x + b.x, a.y + b.y, a.z + b.z, a.w + b.w);
}

// ---------------- bf16-split tensor GEMM, double-buffered ----------------
// C[M,N] = act(A@B + bias + Add). B row-major [K,N]. BM=128, BK=32, 256 thr.
// smem word layout per buffer: slot (s*4+t) holds k-pairs (s*8+t) [.x=hi,.y=lo]
// and (s*8+t+4) [.z=hi,.w=lo]; index ((slot)*DIM + rc)*4 + comp.
template<int BN, int ACT, bool HAS_BIAS, bool HAS_ADD, bool ADD_IDX>
__global__ void __launch_bounds__(256)
tgemm(const float* __restrict__ A, const float* __restrict__ B,
      const float* __restrict__ bias, const float* __restrict__ Add,
      const int* __restrict__ addIdx, float* __restrict__ C,
      int M, int N, int K)
{
    constexpr int BM = 128;
    constexpr int WN = BN / 4, MT = 4, NT = WN / 8;
    constexpr int KC = BN / 8;               // B floats per thread per tile

    extern __shared__ uint32_t dynsm[];
    uint32_t* AsW[2] = { dynsm, dynsm + BM * 32 };
    uint32_t* BsW[2] = { dynsm + 2 * BM * 32, dynsm + 2 * BM * 32 + BN * 32 };

    int tid = threadIdx.x, lane = tid & 31, w = tid >> 5;
    int g = lane >> 2, tg = lane & 3;
    int wM = w >> 2, wN = w & 3;
    int m0 = blockIdx.y * BM, n0 = blockIdx.x * BN;

    float acc[MT][NT][4];
#pragma unroll
    for (int mt = 0; mt < MT; mt++)
#pragma unroll
        for (int nt = 0; nt < NT; nt++)
#pragma unroll
            for (int c = 0; c < 4; c++) acc[mt][nt][c] = 0.f;

    int arow = tid >> 1, ahalf = tid & 1;
    int bn = tid % BN, bq = tid / BN, kb = bq * KC;

    float sa[16], sb[KC];

    auto ldA = [&](int k0) {
        const float* p = A + (size_t)(m0 + arow) * K + k0 + ahalf * 16;
#pragma unroll
        for (int j = 0; j < 16; j += 4) *(float4*)&sa[j] = *(const float4*)(p + j);
    };
    auto ldB = [&](int k0) {
#pragma unroll
        for (int j = 0; j < KC; j++) sb[j] = B[(size_t)(k0 + kb + j) * N + n0 + bn];
    };
    auto stA = [&](int buf) {
#pragma unroll
        for (int j = 0; j < 16; j += 2) {
            int p = (ahalf * 16 + j) >> 1, s = p >> 3, lp = p & 7, t = lp & 3;
            int off = (lp & 4) ? 2 : 0;
            uint32_t hi, lo; splitpair(sa[j], sa[j + 1], hi, lo);
            uint32_t* d = &AsW[buf][(((s << 2) | t) * BM + arow) * 4 + off];
            d[0] = hi; d[1] = lo;
        }
    };
    auto stB = [&](int buf) {
#pragma unroll
        for (int j = 0; j < KC; j += 2) {
            int p = (kb + j) >> 1, s = p >> 3, lp = p & 7, t = lp & 3;
            int off = (lp & 4) ? 2 : 0;
            uint32_t hi, lo; splitpair(sb[j], sb[j + 1], hi, lo);
            uint32_t* d = &BsW[buf][(((s << 2) | t) * BN + bn) * 4 + off];
            d[0] = hi; d[1] = lo;
        }
    };

    int KT = K / 32;
    ldA(0); ldB(0); stA(0); stB(0);
    __syncthreads();
    for (int kt = 0; kt < KT; kt++) {
        int cur = kt & 1;
        if (kt + 1 < KT) { ldA((kt + 1) * 32); ldB((kt + 1) * 32); }
        const uint4* A4 = (const uint4*)AsW[cur];
        const uint4* B4 = (const uint4*)BsW[cur];
#pragma unroll
        for (int s = 0; s < 2; s++) {
            uint4 af[MT][2], bf[NT];
#pragma unroll
            for (int mt = 0; mt < MT; mt++) {
                int mr = wM * 64 + mt * 16 + g;
                af[mt][0] = A4[(s * 4 + tg) * BM + mr];
                af[mt][1] = A4[(s * 4 + tg) * BM + mr + 8];
            }
#pragma unroll
            for (int nt = 0; nt < NT; nt++)
                bf[nt] = B4[(s * 4 + tg) * BN + wN * WN + nt * 8 + g];
#pragma unroll
            for (int mt = 0; mt < MT; mt++)
#pragma unroll
                for (int nt = 0; nt < NT; nt++) {
                    mma16(acc[mt][nt], af[mt][0].x, af[mt][1].x, af[mt][0].z, af[mt][1].z,
                          bf[nt].x, bf[nt].z);
                    mma16(acc[mt][nt], af[mt][0].x, af[mt][1].x, af[mt][0].z, af[mt][1].z,
                          bf[nt].y, bf[nt].w);
                    mma16(acc[mt][nt], af[mt][0].y, af[mt][1].y, af[mt][0].w, af[mt][1].w,
                          bf[nt].x, bf[nt].z);
                }
        }
        if (kt + 1 < KT) { stA((kt + 1) & 1); stB((kt + 1) & 1); }
        __syncthreads();
    }

#pragma unroll
    for (int mt = 0; mt < MT; mt++) {
        int r1 = m0 + wM * 64 + mt * 16 + g;
        int r2 = r1 + 8;
        int a1 = r1, a2 = r2;
        if (HAS_ADD && ADD_IDX) { a1 = addIdx[r1]; a2 = addIdx[r2]; }
#pragma unroll
        for (int nt = 0; nt < NT; nt++) {
            int cb = n0 + wN * WN + nt * 8 + 2 * tg;
            float e0 = acc[mt][nt][0], e1 = acc[mt][nt][1];
            float e2 = acc[mt][nt][2], e3 = acc[mt][nt][3];
            if (HAS_BIAS) { float b0 = bias[cb], b1 = bias[cb + 1]; e0 += b0; e1 += b1; e2 += b0; e3 += b1; }
            if (HAS_ADD) {
                e0 += Add[(size_t)a1 * N + cb]; e1 += Add[(size_t)a1 * N + cb + 1];
                e2 += Add[(size_t)a2 * N + cb]; e3 += Add[(size_t)a2 * N + cb + 1];
            }
            if (ACT == 1) { e0 = fmaxf(e0, 0.f); e1 = fmaxf(e1, 0.f); e2 = fmaxf(e2, 0.f); e3 = fmaxf(e3, 0.f); }
            if (ACT == 2) { e0 = gelu_f(e0); e1 = gelu_f(e1); e2 = gelu_f(e2); e3 = gelu_f(e3); }
            *(float2*)(C + (size_t)r1 * N + cb) = make_float2(e0, e1);
            *(float2*)(C + (size_t)r2 * N + cb) = make_float2(e2, e3);
        }
    }
}

// ---------------- attention ----------------
__global__ void __launch_bounds__(256)
k_attn(const float* __restrict__ Q, const float* __restrict__ Km,
       const float* __restrict__ V, float* __restrict__ O)
{
    int e = blockIdx.x;
    int tid = threadIdx.x;
    __shared__ float qs[8][DG], ks[8][DG], vs[8][DG];
    __shared__ float att[NH][8][8];

    for (int i = tid; i < 8 * DG; i += 256) {
        int s = i >> 8, c = i & 255;
        size_t base = (size_t)(e * 8 + s) * DG + c;
        qs[s][c] = Q[base]; ks[s][c] = Km[base]; vs[s][c] = V[base];
    }
    __syncthreads();
    {
        int h = tid >> 6, rem = tid & 63, qi = rem >> 3, ki = rem & 7;
        float acc = 0.f;
#pragma unroll
        for (int d = 0; d < HD; d++) acc = fmaf(qs[qi][h * HD + d], ks[ki][h * HD + d], acc);
        att[h][qi][ki] = acc * 0.125f;
    }
    __syncthreads();
    if (tid < 32) {
        int h = tid >> 3, qi = tid & 7;
        float m = -1e30f;
#pragma unroll
        for (int ki = 0; ki < 8; ki++) m = fmaxf(m, att[h][qi][ki]);
        float s = 0.f, ex[8];
#pragma unroll
        for (int ki = 0; ki < 8; ki++) { ex[ki] = __expf(att[h][qi][ki] - m); s += ex[ki]; }
        float inv = 1.f / s;
#pragma unroll
        for (int ki = 0; ki < 8; ki++) att[h][qi][ki] = ex[ki] * inv;
    }
    __syncthreads();
    {
        int c = tid, h = c >> 6;
#pragma unroll
        for (int s = 0; s < 8; s++) {
            float acc = 0.f;
#pragma unroll
            for (int ki = 0; ki < 8; ki++) acc = fmaf(att[h][s][ki], vs[ki][c], acc);
            O[(size_t)(e * 8 + s) * DG + c] = acc;
        }
    }
}

// ---------------- fused lm_head + softmax (recompute 2-pass) ----------------
// grid = NROWS/128 CTAs, 256 threads. A (Y[128x64]) split-resident in smem.
// dyn smem: AsW 16 slots*128*4 words (32KB) + BsW 2 * 16*128*4 (64KB).
__global__ void __launch_bounds__(256, 1)
flm(const float* __restrict__ Y, const float* __restrict__ emb, float* __restrict__ probs)
{
    constexpr int BM = 128, BN = 128, MT = 4, NT = 4, NTILE = (VOCAB + 127) / 128;

    extern __shared__ uint32_t dynsm[];
    uint32_t* AsW = dynsm;                                     // 16*BM*4 = 8192 words
    uint32_t* BsW[2] = { dynsm + 8192, dynsm + 16384 };        // each 16*BN*4

    __shared__ float2 red[4][BM];
    __shared__ float Ms[BM], Is[BM];

    int tid = threadIdx.x, lane = tid & 31, w = tid >> 5;
    int g = lane >> 2, tg = lane & 3;
    int wM = w >> 2, wN = w & 3;
    int m0 = blockIdx.x * BM;

    // ---- load + split A once (K=64: slots s=0..3) ----
    {
        int row = tid >> 1, half = tid & 1;
        const float* ap = Y + (size_t)(m0 + row) * 64 + half * 32;
        float sa[32];
#pragma unroll
        for (int j = 0; j < 32; j += 4) *(float4*)&sa[j] = *(const float4*)(ap + j);
#pragma unroll
        for (int j = 0; j < 32; j += 2) {
            int p = (half * 32 + j) >> 1, s = p >> 3, lp = p & 7, t = lp & 3;
            int off = (lp & 4) ? 2 : 0;
            uint32_t hi, lo; splitpair(sa[j], sa[j + 1], hi, lo);
            uint32_t* d = &AsW[(((s << 2) | t) * BM + row) * 4 + off];
            d[0] = hi; d[1] = lo;
        }
    }

    int bn = tid & 127, bq = tid >> 7;      // bq: k-half (32 ks)
    float sb[32];
    auto ldB = [&](int tile) {
        int n = tile * 128 + bn;
        if (n < VOCAB) {
            const float* bp = emb + (size_t)n * 64 + bq * 32;
#pragma unroll
            for (int j = 0; j < 32; j += 4) *(float4*)&sb[j] = *(const float4*)(bp + j);
        } else {
#pragma unroll
            for (int j = 0; j < 32; j++) sb[j] = 0.f;
        }
    };
    auto stB = [&](int buf) {
#pragma unroll
        for (int j = 0; j < 32; j += 2) {
            int p = (bq * 32 + j) >> 1, s = p >> 3, lp = p & 7, t = lp & 3;
            int off = (lp & 4) ? 2 : 0;
            uint32_t hi, lo; splitpair(sb[j], sb[j + 1], hi, lo);
            uint32_t* d = &BsW[buf][(((s << 2) | t) * BN + bn) * 4 + off];
            d[0] = hi; d[1] = lo;
        }
    };
    auto compute = [&](int buf, float acc[MT][NT][4]) {
        const uint4* A4 = (const uint4*)AsW;
        const uint4* B4 = (const uint4*)BsW[buf];
#pragma unroll
        for (int s = 0; s < 4; s++) {
            uint4 af[MT][2], bf[NT];
#pragma unroll
            for (int mt = 0; mt < MT; mt++) {
                int mr = wM * 64 + mt * 16 + g;
                af[mt][0] = A4[(s * 4 + tg) * BM + mr];
                af[mt][1] = A4[(s * 4 + tg) * BM + mr + 8];
            }
#pragma unroll
            for (int nt = 0; nt < NT; nt++)
                bf[nt] = B4[(s * 4 + tg) * BN + wN * 32 + nt * 8 + g];
#pragma unroll
            for (int mt = 0; mt < MT; mt++)
#pragma unroll
                for (int nt = 0; nt < NT; nt++) {
                    mma16(acc[mt][nt], af[mt][0].x, af[mt][1].x, af[mt][0].z, af[mt][1].z,
                          bf[nt].x, bf[nt].z);
                    mma16(acc[mt][nt], af[mt][0].x, af[mt][1].x, af[mt][0].z, af[mt][1].z,
                          bf[nt].y, bf[nt].w);
                    mma16(acc[mt][nt], af[mt][0].y, af[mt][1].y, af[mt][0].w, af[mt][1].w,
                          bf[nt].x, bf[nt].z);
                }
        }
    };

    float mreg[8], sreg[8];
#pragma unroll
    for (int i = 0; i < 8; i++) { mreg[i] = -1e30f; sreg[i] = 0.f; }

    // ---- pass 1: stats ----
    ldB(0); stB(0);
    __syncthreads();
    for (int tile = 0; tile < NTILE; tile++) {
        int cur = tile & 1;
        if (tile + 1 < NTILE) ldB(tile + 1);
        float acc[MT][NT][4];
#pragma unroll
        for (int mt = 0; mt < MT; mt++)
#pragma unroll
            for (int nt = 0; nt < NT; nt++)
#pragma unroll
                for (int c = 0; c < 4; c++) acc[mt][nt][c] = 0.f;
        compute(cur, acc);
#pragma unroll
        for (int mt = 0; mt < MT; mt++)
#pragma unroll
            for (int nt = 0; nt < NT; nt++) {
                int col = tile * 128 + wN * 32 + nt * 8 + 2 * tg;
                if (col < VOCAB) {
                    upd_stats(mreg[mt * 2], sreg[mt * 2], acc[mt][nt][0]);
                    upd_stats(mreg[mt * 2], sreg[mt * 2], acc[mt][nt][1]);
                    upd_stats(mreg[mt * 2 + 1], sreg[mt * 2 + 1], acc[mt][nt][2]);
                    upd_stats(mreg[mt * 2 + 1], sreg[mt * 2 + 1], acc[mt][nt][3]);
                }
            }
        if (tile + 1 < NTILE) stB(cur ^ 1);
        __syncthreads();
    }

    // ---- reduce stats: quad (tg) then across wN warps ----
#pragma unroll
    for (int i = 0; i < 8; i++) {
#pragma unroll
        for (int d = 1; d < 4; d <<= 1) {
            float om = __shfl_xor_sync(0xffffffffu, mreg[i], d);
            float os = __shfl_xor_sync(0xffffffffu, sreg[i], d);
            float M = fmaxf(mreg[i], om);
            sreg[i] = sreg[i] * __expf(mreg[i] - M) + os * __expf(om - M);
            mreg[i] = M;
        }
    }
    if (tg == 0) {
#pragma unroll
        for (int mt = 0; mt < MT; mt++)
#pragma unroll
            for (int h = 0; h < 2; h++)
                red[wN][wM * 64 + mt * 16 + h * 8 + g] =
                    make_float2(mreg[mt * 2 + h], sreg[mt * 2 + h]);
    }
    __syncthreads();
    if (tid < BM) {
        float M = -1e30f, S = 0.f;
#pragma unroll
        for (int j = 0; j < 4; j++) {
            float2 r = red[j][tid];
            float nM = fmaxf(M, r.x);
            S = S * __expf(M - nM) + r.y * __expf(r.x - nM);
            M = nM;
        }
        Ms[tid] = M; Is[tid] = 1.f / S;
    }
    __syncthreads();

    // ---- pass 2: recompute + write probs ----
    ldB(0); stB(0);
    __syncthreads();
    for (int tile = 0; tile < NTILE; tile++) {
        int cur = tile & 1;
        if (tile + 1 < NTILE) ldB(tile + 1);
        float acc[MT][NT][4];
#pragma unroll
        for (int mt = 0; mt < MT; mt++)
#pragma unroll
            for (int nt = 0; nt < NT; nt++)
#pragma unroll
                for (int c = 0; c < 4; c++) acc[mt][nt][c] = 0.f;
        compute(cur, acc);
#pragma unroll
        for (int mt = 0; mt < MT; mt++) {
            int rl0 = wM * 64 + mt * 16 + g, rl1 = rl0 + 8;
            float M0 = Ms[rl0], I0 = Is[rl0], M1 = Ms[rl1], I1 = Is[rl1];
#pragma unroll
            for (int nt = 0; nt < NT; nt++) {
                int col = tile * 128 + wN * 32 + nt * 8 + 2 * tg;
                if (col < VOCAB) {
                    float p0 = __expf(acc[mt][nt][0] - M0) * I0;
                    float p1 = __expf(acc[mt][nt][1] - M0) * I0;
                    float p2 = __expf(acc[mt][nt][2] - M1) * I1;
                    float p3 = __expf(acc[mt][nt][3] - M1) * I1;
                    *(float2*)(probs + (size_t)(m0 + rl0) * VOCAB + col) = make_float2(p0, p1);
                    *(float2*)(probs + (size_t)(m0 + rl1) * VOCAB + col) = make_float2(p2, p3);
                }
            }
        }
        if (tile + 1 < NTILE) stB(cur ^ 1);
        __syncthreads();
    }
}

// ---------------- host launcher ----------------
extern "C" void kernel_launch(void* const* d_in, const int* in_sizes, int n_in,
                              void* d_out, int out_size)
{
    const int*   node_tokens = (const int*)d_in[0];
    const int*   edge_tokens = (const int*)d_in[1];
    const int*   edge_index  = (const int*)d_in[2];
    const int*   mask_rows   = (const int*)d_in[3];
    const float* emb   = (const float*)d_in[4];
    const float* W_msg = (const float*)d_in[5];
    const float* W_node= (const float*)d_in[6];
    const float* lc1_w = (const float*)d_in[7];
    const float* lc1_b = (const float*)d_in[8];
    const float* lc2_w = (const float*)d_in[9];
    const float* lc2_b = (const float*)d_in[10];
    const float* Wq  = (const float*)d_in[11];
    const float* Wk  = (const float*)d_in[12];
    const float* Wv  = (const float*)d_in[13];
    const float* Wo  = (const float*)d_in[14];
    const float* Wf1 = (const float*)d_in[15];
    const float* Wf2 = (const float*)d_in[16];
    const int* src = edge_index;
    const int* dst = edge_index + N_EDGES;

    float *p_x, *p_e, *p_msg, *p_agg, *p_h, *p_zin, *p_zg, *p_q, *p_k, *p_v,
          *p_ao, *p_x1, *p_ffn, *p_x2, *p_y;
    int *p_mtok;
    cudaGetSymbolAddress((void**)&p_x,   g_x);
    cudaGetSymbolAddress((void**)&p_e,   g_e);
    cudaGetSymbolAddress((void**)&p_msg, g_msg);
    cudaGetSymbolAddress((void**)&p_agg, g_agg);
    cudaGetSymbolAddress((void**)&p_h,   g_h);
    cudaGetSymbolAddress((void**)&p_zin, g_zin);
    cudaGetSymbolAddress((void**)&p_zg,  g_zg);
    cudaGetSymbolAddress((void**)&p_q,   g_q);
    cudaGetSymbolAddress((void**)&p_k,   g_k);
    cudaGetSymbolAddress((void**)&p_v,   g_v);
    cudaGetSymbolAddress((void**)&p_ao,  g_ao);
    cudaGetSymbolAddress((void**)&p_x1,  g_x1);
    cudaGetSymbolAddress((void**)&p_ffn, g_ffn);
    cudaGetSymbolAddress((void**)&p_x2,  g_x2);
    cudaGetSymbolAddress((void**)&p_y,   g_y);
    cudaGetSymbolAddress((void**)&p_mtok, g_mtok);

    // dynamic smem sizes
    const int SM128 = 2 * 128 * 32 * 4 + 2 * 128 * 32 * 4;   // 64KB
    const int SM64  = 2 * 128 * 32 * 4 + 2 * 64 * 32 * 4;    // 48KB
    const int SMFLM = (8192 + 2 * 8192) * 4;                 // 96KB
    cudaFuncSetAttribute(tgemm<128, 1, false, true, true>,  cudaFuncAttributeMaxDynamicSharedMemorySize, SM128);
    cudaFuncSetAttribute(tgemm<128, 1, false, true, false>, cudaFuncAttributeMaxDynamicSharedMemorySize, SM128);
    cudaFuncSetAttribute(tgemm<128, 0, true, false, false>, cudaFuncAttributeMaxDynamicSharedMemorySize, SM128);
    cudaFuncSetAttribute(tgemm<128, 0, false, false, false>,cudaFuncAttributeMaxDynamicSharedMemorySize, SM128);
    cudaFuncSetAttribute(tgemm<128, 0, false, true, false>, cudaFuncAttributeMaxDynamicSharedMemorySize, SM128);
    cudaFuncSetAttribute(tgemm<128, 2, false, false, false>,cudaFuncAttributeMaxDynamicSharedMemorySize, SM128);
    cudaFuncSetAttribute(tgemm<64, 0, true, false, false>,  cudaFuncAttributeMaxDynamicSharedMemorySize, SM64);
    cudaFuncSetAttribute(flm, cudaFuncAttributeMaxDynamicSharedMemorySize, SMFLM);

    // output layout: probs-only, or labels(16384) ++ probs
    float* out = (float*)d_out;
    const long long PROBS_N = (long long)NROWS * VOCAB;
    float* labels_out = nullptr;
    float* probs = out;
    if ((long long)out_size >= PROBS_N + NROWS) { labels_out = out; probs = out + NROWS; }

    // 1) masking + embeddings
    k_labels<<<NROWS / 256, 256>>>(edge_tokens, mask_rows, labels_out);
    k_embed<<<(N_NODES * L_TOK * 16) / 256, 256>>>(node_tokens, emb, p_x, N_NODES * L_TOK * 16);
    k_embed<<<(N_EDGES * L_TOK * 16) / 256, 256>>>(p_mtok, emb, p_e, N_EDGES * L_TOK * 16);
    k_zero<<<(N_NODES * FD / 4) / 256, 256>>>(p_agg, N_NODES * FD / 4);

    // 2) GNN
    tgemm<128, 1, false, true, true><<<dim3(FD / 128, N_EDGES / 128), 256, SM128>>>(
        p_e, W_msg, nullptr, p_x, src, p_msg, N_EDGES, FD, FD);
    k_scatter<<<(N_EDGES * FD) / 256, 256>>>(p_msg, dst, p_agg);
    tgemm<128, 1, false, true, false><<<dim3(FD / 128, N_NODES / 128), 256, SM128>>>(
        p_x, W_node, nullptr, p_agg, nullptr, p_h, N_NODES, FD, FD);

    // 3) eh gather + lc1
    k_zin<<<(NROWS * 16) / 256, 256>>>(p_h, src, dst, p_zin);
    tgemm<128, 0, true, false, false><<<dim3(DG / 128, NROWS / 128), 256, SM128>>>(
        p_zin, lc1_w, lc1_b, nullptr, nullptr, p_zg, NROWS, DG, D_EMB);

    // 4) transformer block
    tgemm<128, 0, false, false, false><<<dim3(DG / 128, NROWS / 128), 256, SM128>>>(
        p_zg, Wq, nullptr, nullptr, nullptr, p_q, NROWS, DG, DG);
    tgemm<128, 0, false, false, false><<<dim3(DG / 128, NROWS / 128), 256, SM128>>>(
        p_zg, Wk, nullptr, nullptr, nullptr, p_k, NROWS, DG, DG);
    tgemm<128, 0, false, false, false><<<dim3(DG / 128, NROWS / 128), 256, SM128>>>(
        p_zg, Wv, nullptr, nullptr, nullptr, p_v, NROWS, DG, DG);
    k_attn<<<N_EDGES, 256>>>(p_q, p_k, p_v, p_ao);
    tgemm<128, 0, false, true, false><<<dim3(DG / 128, NROWS / 128), 256, SM128>>>(
        p_ao, Wo, nullptr, p_zg, nullptr, p_x1, NROWS, DG, DG);
    tgemm<128, 2, false, false, false><<<dim3(4 * DG / 128, NROWS / 128), 256, SM128>>>(
        p_x1, Wf1, nullptr, nullptr, nullptr, p_ffn, NROWS, 4 * DG, DG);
    tgemm<128, 0, false, true, false><<<dim3(DG / 128, NROWS / 128), 256, SM128>>>(
        p_ffn, Wf2, nullptr, p_x1, nullptr, p_x2, NROWS, DG, 4 * DG);

    // 5) lc2
    tgemm<64, 0, true, false, false><<<dim3(1, NROWS / 128), 256, SM64>>>(
        p_x2, lc2_w, lc2_b, nullptr, nullptr, p_y, NROWS, D_EMB, DG);

    // 6) fused tied lm head + softmax
    flm<<<NROWS / 128, 256, SMFLM>>>(p_y, emb, probs);
}

// round 5
// speedup vs baseline: 2.0708x; 1.2334x over previous
#include <cuda_runtime.h>
#include <cuda_bf16.h>
#include <math.h>
#include <stdint.h>

// ---------------- problem constants ----------------
#define N_NODES 8192
#define N_EDGES 2048
#define L_TOK   8
#define D_EMB   64
#define FD      512
#define DG      256
#define NH      4
#define HD      64
#define VOCAB   10000
#define NROWS   (N_EDGES * L_TOK)   // 16384

// ---------------- scratch ----------------
__device__ float g_x  [N_NODES * FD];
__device__ float g_e  [N_EDGES * FD];
__device__ float g_msg[N_EDGES * FD];
__device__ float g_agg[N_NODES * FD];
__device__ float g_h  [N_NODES * FD];
__device__ float g_zin[NROWS * D_EMB];
__device__ float g_zg [NROWS * DG];
__device__ float g_q  [NROWS * DG];
__device__ float g_k  [NROWS * DG];
__device__ float g_v  [NROWS * DG];
__device__ float g_ao [NROWS * DG];
__device__ float g_x1 [NROWS * DG];
__device__ float g_ffn[NROWS * 4 * DG];
__device__ float g_x2 [NROWS * DG];
__device__ float g_y  [NROWS * D_EMB];

// pre-split weight planes (packed bf16x2: word = {bf16(k), bf16(k+1)})
#define OFF_WMSG  0
#define OFF_WNODE (OFF_WMSG  + 256*512)
#define OFF_LC1   (OFF_WNODE + 256*512)
#define OFF_WQ    (OFF_LC1   + 32*256)
#define OFF_WK    (OFF_WQ    + 128*256)
#define OFF_WV    (OFF_WK    + 128*256)
#define OFF_WO    (OFF_WV    + 128*256)
#define OFF_WF1   (OFF_WO    + 128*256)
#define OFF_WF2   (OFF_WF1   + 128*1024)
#define OFF_LC2   (OFF_WF2   + 512*256)
#define OFF_EMB   (OFF_LC2   + 128*64)
#define TOTAL_PAIRS (OFF_EMB + VOCAB*32)
__device__ uint32_t g_whi[TOTAL_PAIRS];
__device__ uint32_t g_wlo[TOTAL_PAIRS];

// ---------------- helpers ----------------
__device__ __forceinline__ void splitpair(float x0, float x1, uint32_t& hi, uint32_t& lo) {
    __nv_bfloat162 h = __floats2bfloat162_rn(x0, x1);
    float h0 = __bfloat162float(h.x), h1 = __bfloat162float(h.y);
    __nv_bfloat162 l = __floats2bfloat162_rn(x0 - h0, x1 - h1);
    hi = *reinterpret_cast<uint32_t*>(&h);
    lo = *reinterpret_cast<uint32_t*>(&l);
}

__device__ __forceinline__ void mma16(float* c,
    uint32_t a0, uint32_t a1, uint32_t a2, uint32_t a3, uint32_t b0, uint32_t b1)
{
    asm volatile(
        "mma.sync.aligned.m16n8k16.row.col.f32.bf16.bf16.f32 "
        "{%0,%1,%2,%3},{%4,%5,%6,%7},{%8,%9},{%0,%1,%2,%3};"
        : "+f"(c[0]), "+f"(c[1]), "+f"(c[2]), "+f"(c[3])
        : "r"(a0), "r"(a1), "r"(a2), "r"(a3), "r"(b0), "r"(b1));
}

__device__ __forceinline__ float gelu_f(float v) {
    float u = 0.7978845608028654f * (v + 0.044715f * v * v * v);
    float t;
    asm("tanh.approx.f32 %0, %1;" : "=f"(t) : "f"(u));
    return 0.5f * v * (1.f + t);
}

__device__ __forceinline__ void upd_stats(float& m, float& s, float x) {
    if (x > m) { s = s * __expf(m - x) + 1.f; m = x; }
    else       { s += __expf(x - m); }
}

// XOR swizzle: octet lanes (tg 0..3) get distinct bank columns
__device__ __forceinline__ int swz(int slot, int rc, int DIM) {
    return slot * DIM + (rc ^ ((slot & 3) << 1));
}

// ---------------- small kernels ----------------
// fused: labels + masked-token edge embedding gather
__global__ void k_lab_embed_e(const int* __restrict__ etok, const int* __restrict__ maskbits,
                              const float* __restrict__ emb, float* __restrict__ labels_out,
                              float* __restrict__ oute)
{
    int i = blockIdx.x * blockDim.x + threadIdx.x;
    if (i >= NROWS * 16) return;
    int slot = i >> 4, d4 = i & 15;
    int e = slot >> 3;
    int tok = etok[slot];
    bool masked = (maskbits[e] != 0) && (tok > 3);
    int mtok = masked ? 4 : tok;
    if (d4 == 0 && labels_out) labels_out[slot] = masked ? (float)tok : -100.0f;
    ((float4*)oute)[i] = ((const float4*)emb)[mtok * 16 + d4];
}

__global__ void k_embed(const int* __restrict__ toks, const float* __restrict__ emb,
                        float* __restrict__ out, int total_f4)
{
    int i = blockIdx.x * blockDim.x + threadIdx.x;
    if (i >= total_f4) return;
    int slot = i >> 4, d4 = i & 15;
    ((float4*)out)[i] = ((const float4*)emb)[toks[slot] * 16 + d4];
}

// weight pre-split (k-major planes; emb n-major)
__device__ __forceinline__ void prep_k(const float* __restrict__ W, int N, int il, int base) {
    int kp = il / N, n = il - kp * N;
    uint32_t hi, lo;
    splitpair(W[(2 * kp) * N + n], W[(2 * kp + 1) * N + n], hi, lo);
    g_whi[base + il] = hi; g_wlo[base + il] = lo;
}

__global__ void k_prep(const float* __restrict__ Wmsg, const float* __restrict__ Wnode,
                       const float* __restrict__ lc1, const float* __restrict__ Wq,
                       const float* __restrict__ Wk, const float* __restrict__ Wv,
                       const float* __restrict__ Wo, const float* __restrict__ Wf1,
                       const float* __restrict__ Wf2, const float* __restrict__ lc2,
                       const float* __restrict__ emb)
{
    int i = blockIdx.x * blockDim.x + threadIdx.x;
    if (i >= TOTAL_PAIRS) return;
    if      (i < OFF_WNODE) prep_k(Wmsg,  512,  i - OFF_WMSG,  OFF_WMSG);
    else if (i < OFF_LC1)   prep_k(Wnode, 512,  i - OFF_WNODE, OFF_WNODE);
    else if (i < OFF_WQ)    prep_k(lc1,   256,  i - OFF_LC1,   OFF_LC1);
    else if (i < OFF_WK)    prep_k(Wq,    256,  i - OFF_WQ,    OFF_WQ);
    else if (i < OFF_WV)    prep_k(Wk,    256,  i - OFF_WK,    OFF_WK);
    else if (i < OFF_WO)    prep_k(Wv,    256,  i - OFF_WV,    OFF_WV);
    else if (i < OFF_WF1)   prep_k(Wo,    256,  i - OFF_WO,    OFF_WO);
    else if (i < OFF_WF2)   prep_k(Wf1,   1024, i - OFF_WF1,   OFF_WF1);
    else if (i < OFF_LC2)   prep_k(Wf2,   256,  i - OFF_WF2,   OFF_WF2);
    else if (i < OFF_EMB)   prep_k(lc2,   64,   i - OFF_LC2,   OFF_LC2);
    else {
        int il = i - OFF_EMB;
        int n = il >> 5, kp = il & 31;
        uint32_t hi, lo;
        splitpair(emb[n * 64 + 2 * kp], emb[n * 64 + 2 * kp + 1], hi, lo);
        g_whi[i] = hi; g_wlo[i] = lo;
    }
}

__global__ void k_zero(float* __restrict__ p, int total_f4)
{
    int i = blockIdx.x * blockDim.x + threadIdx.x;
    if (i < total_f4) ((float4*)p)[i] = make_float4(0.f, 0.f, 0.f, 0.f);
}

__global__ void k_scatter(const float* __restrict__ msg, const int* __restrict__ dst,
                          float* __restrict__ agg)
{
    int t = blockIdx.x * blockDim.x + threadIdx.x;
    if (t >= N_EDGES * FD) return;
    int e = t >> 9, c = t & 511;
    atomicAdd(&agg[dst[e] * FD + c], msg[t]);
}

__global__ void k_zin(const float* __restrict__ h, const int* __restrict__ src,
                      const int* __restrict__ dst, float* __restrict__ zin)
{
    int i = blockIdx.x * blockDim.x + threadIdx.x;
    if (i >= NROWS * 16) return;
    int r = i >> 4, d4 = i & 15;
    int e = r >> 3, l = r & 7;
    const float4* h4 = (const float4*)h;
    float4 a = h4[src[e] * 128 + l * 16 + d4];
    float4 b = h4[dst[e] * 128 + l * 16 + d4];
    ((float4*)zin)[i] = make_float4(a.x + b.x, a.y + b.y, a.z + b.z, a.w + b.w);
}

// ---------------- bf16-split tensor GEMM, double-buffered, swizzled ----------------
// C[M,N] = act(A@B + bias + Add). B given as pre-split k-major planes.
template<int BN, int ACT, bool HAS_BIAS, bool HAS_ADD, bool ADD_IDX>
__global__ void __launch_bounds__(256)
tgemm(const float* __restrict__ A,
      const uint32_t* __restrict__ Bhi, const uint32_t* __restrict__ Blo,
      const float* __restrict__ bias, const float* __restrict__ Add,
      const int* __restrict__ addIdx, float* __restrict__ C,
      int M, int N, int K)
{
    constexpr int BM = 128;
    constexpr int WN = BN / 4, MT = 4, NT = WN / 8;
    constexpr int KC = BN / 8;              // B floats per thread per tile
    constexpr int JP = KC / 2;              // packed words per plane per thread

    extern __shared__ uint32_t dynsm[];
    uint32_t* AsW[2] = { dynsm, dynsm + BM * 32 };
    uint32_t* BsW[2] = { dynsm + 2 * BM * 32, dynsm + 2 * BM * 32 + BN * 32 };

    int tid = threadIdx.x, lane = tid & 31, w = tid >> 5;
    int g = lane >> 2, tg = lane & 3;
    int wM = w >> 2, wN = w & 3;
    int m0 = blockIdx.y * BM, n0 = blockIdx.x * BN;

    float acc[MT][NT][4];
#pragma unroll
    for (int mt = 0; mt < MT; mt++)
#pragma unroll
        for (int nt = 0; nt < NT; nt++)
#pragma unroll
            for (int c = 0; c < 4; c++) acc[mt][nt][c] = 0.f;

    int arow = tid >> 1, ahalf = tid & 1;
    int bn = tid % BN, bq = tid / BN, kb = bq * KC;

    float sa[16];
    uint32_t hw[JP], lw[JP];

    auto ldA = [&](int k0) {
        const float* p = A + (size_t)(m0 + arow) * K + k0 + ahalf * 16;
#pragma unroll
        for (int j = 0; j < 16; j += 4) *(float4*)&sa[j] = *(const float4*)(p + j);
    };
    auto ldB = [&](int k0) {
        int kp0 = (k0 + kb) >> 1;
#pragma unroll
        for (int jp = 0; jp < JP; jp++) {
            size_t idx = (size_t)(kp0 + jp) * N + n0 + bn;
            hw[jp] = Bhi[idx]; lw[jp] = Blo[idx];
        }
    };
    auto stA = [&](int buf) {
#pragma unroll
        for (int j = 0; j < 16; j += 2) {
            int p = (ahalf * 16 + j) >> 1, s = p >> 3, lp = p & 7, t = lp & 3;
            int off = (lp & 4) ? 2 : 0;
            uint32_t hi, lo; splitpair(sa[j], sa[j + 1], hi, lo);
            *(uint2*)&AsW[buf][swz((s << 2) | t, arow, BM) * 4 + off] = make_uint2(hi, lo);
        }
    };
    auto stB = [&](int buf) {
#pragma unroll
        for (int jp = 0; jp < JP; jp++) {
            int p = (kb >> 1) + jp, s = p >> 3, lp = p & 7, t = lp & 3;
            int off = (lp & 4) ? 2 : 0;
            *(uint2*)&BsW[buf][swz((s << 2) | t, bn, BN) * 4 + off] = make_uint2(hw[jp], lw[jp]);
        }
    };

    int KT = K / 32;
    ldA(0); ldB(0); stA(0); stB(0);
    __syncthreads();
    for (int kt = 0; kt < KT; kt++) {
        int cur = kt & 1;
        if (kt + 1 < KT) { ldA((kt + 1) * 32); ldB((kt + 1) * 32); }
        const uint4* A4 = (const uint4*)AsW[cur];
        const uint4* B4 = (const uint4*)BsW[cur];
#pragma unroll
        for (int s = 0; s < 2; s++) {
            uint4 af[MT][2], bf[NT];
#pragma unroll
            for (int mt = 0; mt < MT; mt++) {
                int mr = wM * 64 + mt * 16 + g;
                af[mt][0] = A4[swz(s * 4 + tg, mr, BM)];
                af[mt][1] = A4[swz(s * 4 + tg, mr + 8, BM)];
            }
#pragma unroll
            for (int nt = 0; nt < NT; nt++)
                bf[nt] = B4[swz(s * 4 + tg, wN * WN + nt * 8 + g, BN)];
#pragma unroll
            for (int mt = 0; mt < MT; mt++)
#pragma unroll
                for (int nt = 0; nt < NT; nt++) {
                    mma16(acc[mt][nt], af[mt][0].x, af[mt][1].x, af[mt][0].z, af[mt][1].z,
                          bf[nt].x, bf[nt].z);
                    mma16(acc[mt][nt], af[mt][0].x, af[mt][1].x, af[mt][0].z, af[mt][1].z,
                          bf[nt].y, bf[nt].w);
                    mma16(acc[mt][nt], af[mt][0].y, af[mt][1].y, af[mt][0].w, af[mt][1].w,
                          bf[nt].x, bf[nt].z);
                }
        }
        if (kt + 1 < KT) { stA((kt + 1) & 1); stB((kt + 1) & 1); }
        __syncthreads();
    }

#pragma unroll
    for (int mt = 0; mt < MT; mt++) {
        int r1 = m0 + wM * 64 + mt * 16 + g;
        int r2 = r1 + 8;
        int a1 = r1, a2 = r2;
        if (HAS_ADD && ADD_IDX) { a1 = addIdx[r1]; a2 = addIdx[r2]; }
#pragma unroll
        for (int nt = 0; nt < NT; nt++) {
            int cb = n0 + wN * WN + nt * 8 + 2 * tg;
            float e0 = acc[mt][nt][0], e1 = acc[mt][nt][1];
            float e2 = acc[mt][nt][2], e3 = acc[mt][nt][3];
            if (HAS_BIAS) { float b0 = bias[cb], b1 = bias[cb + 1]; e0 += b0; e1 += b1; e2 += b0; e3 += b1; }
            if (HAS_ADD) {
                e0 += Add[(size_t)a1 * N + cb]; e1 += Add[(size_t)a1 * N + cb + 1];
                e2 += Add[(size_t)a2 * N + cb]; e3 += Add[(size_t)a2 * N + cb + 1];
            }
            if (ACT == 1) { e0 = fmaxf(e0, 0.f); e1 = fmaxf(e1, 0.f); e2 = fmaxf(e2, 0.f); e3 = fmaxf(e3, 0.f); }
            if (ACT == 2) { e0 = gelu_f(e0); e1 = gelu_f(e1); e2 = gelu_f(e2); e3 = gelu_f(e3); }
            *(float2*)(C + (size_t)r1 * N + cb) = make_float2(e0, e1);
            *(float2*)(C + (size_t)r2 * N + cb) = make_float2(e2, e3);
        }
    }
}

// ---------------- attention ----------------
__global__ void __launch_bounds__(256)
k_attn(const float* __restrict__ Q, const float* __restrict__ Km,
       const float* __restrict__ V, float* __restrict__ O)
{
    int e = blockIdx.x;
    int tid = threadIdx.x;
    __shared__ float qs[8][DG], ks[8][DG], vs[8][DG];
    __shared__ float att[NH][8][8];

    for (int i = tid; i < 8 * DG; i += 256) {
        int s = i >> 8, c = i & 255;
        size_t base = (size_t)(e * 8 + s) * DG + c;
        qs[s][c] = Q[base]; ks[s][c] = Km[base]; vs[s][c] = V[base];
    }
    __syncthreads();
    {
        int h = tid >> 6, rem = tid & 63, qi = rem >> 3, ki = rem & 7;
        float acc = 0.f;
#pragma unroll
        for (int d = 0; d < HD; d++) acc = fmaf(qs[qi][h * HD + d], ks[ki][h * HD + d], acc);
        att[h][qi][ki] = acc * 0.125f;
    }
    __syncthreads();
    if (tid < 32) {
        int h = tid >> 3, qi = tid & 7;
        float m = -1e30f;
#pragma unroll
        for (int ki = 0; ki < 8; ki++) m = fmaxf(m, att[h][qi][ki]);
        float s = 0.f, ex[8];
#pragma unroll
        for (int ki = 0; ki < 8; ki++) { ex[ki] = __expf(att[h][qi][ki] - m); s += ex[ki]; }
        float inv = 1.f / s;
#pragma unroll
        for (int ki = 0; ki < 8; ki++) att[h][qi][ki] = ex[ki] * inv;
    }
    __syncthreads();
    {
        int c = tid, h = c >> 6;
#pragma unroll
        for (int s = 0; s < 8; s++) {
            float acc = 0.f;
#pragma unroll
            for (int ki = 0; ki < 8; ki++) acc = fmaf(att[h][s][ki], vs[ki][c], acc);
            O[(size_t)(e * 8 + s) * DG + c] = acc;
        }
    }
}

// ---------------- fused lm_head + softmax (recompute 2-pass, swizzled, presplit emb) ----------------
__global__ void __launch_bounds__(256, 1)
flm(const float* __restrict__ Y, const uint32_t* __restrict__ Ehi,
    const uint32_t* __restrict__ Elo, float* __restrict__ probs)
{
    constexpr int BM = 128, BN = 128, MT = 4, NT = 4, NTILE = (VOCAB + 127) / 128;

    extern __shared__ uint32_t dynsm[];
    uint32_t* AsW = dynsm;                                   // 16*BM*4 words
    uint32_t* BsW[2] = { dynsm + 8192, dynsm + 16384 };

    __shared__ float2 red[4][BM];
    __shared__ float Ms[BM], Is[BM];

    int tid = threadIdx.x, lane = tid & 31, w = tid >> 5;
    int g = lane >> 2, tg = lane & 3;
    int wM = w >> 2, wN = w & 3;
    int m0 = blockIdx.x * BM;

    // ---- load + split A once (K=64) ----
    {
        int row = tid >> 1, half = tid & 1;
        const float* ap = Y + (size_t)(m0 + row) * 64 + half * 32;
        float sa[32];
#pragma unroll
        for (int j = 0; j < 32; j += 4) *(float4*)&sa[j] = *(const float4*)(ap + j);
#pragma unroll
        for (int j = 0; j < 32; j += 2) {
            int p = (half * 32 + j) >> 1, s = p >> 3, lp = p & 7, t = lp & 3;
            int off = (lp & 4) ? 2 : 0;
            uint32_t hi, lo; splitpair(sa[j], sa[j + 1], hi, lo);
            *(uint2*)&AsW[swz((s << 2) | t, row, BM) * 4 + off] = make_uint2(hi, lo);
        }
    }

    int bn = tid & 127, bq = tid >> 7;
    uint32_t hw[16], lw[16];
    auto ldB = [&](int tile) {
        int n = tile * 128 + bn;
        if (n < VOCAB) {
            const uint4* hp = (const uint4*)(Ehi + n * 32 + bq * 16);
            const uint4* lp = (const uint4*)(Elo + n * 32 + bq * 16);
#pragma unroll
            for (int q = 0; q < 4; q++) {
                *(uint4*)&hw[q * 4] = hp[q];
                *(uint4*)&lw[q * 4] = lp[q];
            }
        } else {
#pragma unroll
            for (int j = 0; j < 16; j++) { hw[j] = 0; lw[j] = 0; }
        }
    };
    auto stB = [&](int buf) {
#pragma unroll
        for (int jj = 0; jj < 16; jj++) {
            int p = bq * 16 + jj, s = p >> 3, lp = p & 7, t = lp & 3;
            int off = (lp & 4) ? 2 : 0;
            *(uint2*)&BsW[buf][swz((s << 2) | t, bn, BN) * 4 + off] = make_uint2(hw[jj], lw[jj]);
        }
    };
    auto compute = [&](int buf, float acc[MT][NT][4]) {
        const uint4* A4 = (const uint4*)AsW;
        const uint4* B4 = (const uint4*)BsW[buf];
#pragma unroll
        for (int s = 0; s < 4; s++) {
            uint4 af[MT][2], bf[NT];
#pragma unroll
            for (int mt = 0; mt < MT; mt++) {
                int mr = wM * 64 + mt * 16 + g;
                af[mt][0] = A4[swz(s * 4 + tg, mr, BM)];
                af[mt][1] = A4[swz(s * 4 + tg, mr + 8, BM)];
            }
#pragma unroll
            for (int nt = 0; nt < NT; nt++)
                bf[nt] = B4[swz(s * 4 + tg, wN * 32 + nt * 8 + g, BN)];
#pragma unroll
            for (int mt = 0; mt < MT; mt++)
#pragma unroll
                for (int nt = 0; nt < NT; nt++) {
                    mma16(acc[mt][nt], af[mt][0].x, af[mt][1].x, af[mt][0].z, af[mt][1].z,
                          bf[nt].x, bf[nt].z);
                    mma16(acc[mt][nt], af[mt][0].x, af[mt][1].x, af[mt][0].z, af[mt][1].z,
                          bf[nt].y, bf[nt].w);
                    mma16(acc[mt][nt], af[mt][0].y, af[mt][1].y, af[mt][0].w, af[mt][1].w,
                          bf[nt].x, bf[nt].z);
                }
        }
    };

    float mreg[8], sreg[8];
#pragma unroll
    for (int i = 0; i < 8; i++) { mreg[i] = -1e30f; sreg[i] = 0.f; }

    // ---- pass 1: stats ----
    ldB(0); stB(0);
    __syncthreads();
    for (int tile = 0; tile < NTILE; tile++) {
        int cur = tile & 1;
        if (tile + 1 < NTILE) ldB(tile + 1);
        float acc[MT][NT][4];
#pragma unroll
        for (int mt = 0; mt < MT; mt++)
#pragma unroll
            for (int nt = 0; nt < NT; nt++)
#pragma unroll
                for (int c = 0; c < 4; c++) acc[mt][nt][c] = 0.f;
        compute(cur, acc);
#pragma unroll
        for (int mt = 0; mt < MT; mt++)
#pragma unroll
            for (int nt = 0; nt < NT; nt++) {
                int col = tile * 128 + wN * 32 + nt * 8 + 2 * tg;
                if (col < VOCAB) {
                    upd_stats(mreg[mt * 2], sreg[mt * 2], acc[mt][nt][0]);
                    upd_stats(mreg[mt * 2], sreg[mt * 2], acc[mt][nt][1]);
                    upd_stats(mreg[mt * 2 + 1], sreg[mt * 2 + 1], acc[mt][nt][2]);
                    upd_stats(mreg[mt * 2 + 1], sreg[mt * 2 + 1], acc[mt][nt][3]);
                }
            }
        if (tile + 1 < NTILE) stB(cur ^ 1);
        __syncthreads();
    }

    // ---- reduce stats ----
#pragma unroll
    for (int i = 0; i < 8; i++) {
#pragma unroll
        for (int d = 1; d < 4; d <<= 1) {
            float om = __shfl_xor_sync(0xffffffffu, mreg[i], d);
            float os = __shfl_xor_sync(0xffffffffu, sreg[i], d);
            float M = fmaxf(mreg[i], om);
            sreg[i] = sreg[i] * __expf(mreg[i] - M) + os * __expf(om - M);
            mreg[i] = M;
        }
    }
    if (tg == 0) {
#pragma unroll
        for (int mt = 0; mt < MT; mt++)
#pragma unroll
            for (int h = 0; h < 2; h++)
                red[wN][wM * 64 + mt * 16 + h * 8 + g] =
                    make_float2(mreg[mt * 2 + h], sreg[mt * 2 + h]);
    }
    __syncthreads();
    if (tid < BM) {
        float M = -1e30f, S = 0.f;
#pragma unroll
        for (int j = 0; j < 4; j++) {
            float2 r = red[j][tid];
            float nM = fmaxf(M, r.x);
            S = S * __expf(M - nM) + r.y * __expf(r.x - nM);
            M = nM;
        }
        Ms[tid] = M; Is[tid] = 1.f / S;
    }
    __syncthreads();

    // ---- pass 2: recompute + write probs ----
    ldB(0); stB(0);
    __syncthreads();
    for (int tile = 0; tile < NTILE; tile++) {
        int cur = tile & 1;
        if (tile + 1 < NTILE) ldB(tile + 1);
        float acc[MT][NT][4];
#pragma unroll
        for (int mt = 0; mt < MT; mt++)
#pragma unroll
            for (int nt = 0; nt < NT; nt++)
#pragma unroll
                for (int c = 0; c < 4; c++) acc[mt][nt][c] = 0.f;
        compute(cur, acc);
#pragma unroll
        for (int mt = 0; mt < MT; mt++) {
            int rl0 = wM * 64 + mt * 16 + g, rl1 = rl0 + 8;
            float M0 = Ms[rl0], I0 = Is[rl0], M1 = Ms[rl1], I1 = Is[rl1];
#pragma unroll
            for (int nt = 0; nt < NT; nt++) {
                int col = tile * 128 + wN * 32 + nt * 8 + 2 * tg;
                if (col < VOCAB) {
                    float p0 = __expf(acc[mt][nt][0] - M0) * I0;
                    float p1 = __expf(acc[mt][nt][1] - M0) * I0;
                    float p2 = __expf(acc[mt][nt][2] - M1) * I1;
                    float p3 = __expf(acc[mt][nt][3] - M1) * I1;
                    *(float2*)(probs + (size_t)(m0 + rl0) * VOCAB + col) = make_float2(p0, p1);
                    *(float2*)(probs + (size_t)(m0 + rl1) * VOCAB + col) = make_float2(p2, p3);
                }
            }
        }
        if (tile + 1 < NTILE) stB(cur ^ 1);
        __syncthreads();
    }
}

// ---------------- host launcher ----------------
extern "C" void kernel_launch(void* const* d_in, const int* in_sizes, int n_in,
                              void* d_out, int out_size)
{
    const int*   node_tokens = (const int*)d_in[0];
    const int*   edge_tokens = (const int*)d_in[1];
    const int*   edge_index  = (const int*)d_in[2];
    const int*   mask_rows   = (const int*)d_in[3];
    const float* emb   = (const float*)d_in[4];
    const float* W_msg = (const float*)d_in[5];
    const float* W_node= (const float*)d_in[6];
    const float* lc1_w = (const float*)d_in[7];
    const float* lc1_b = (const float*)d_in[8];
    const float* lc2_w = (const float*)d_in[9];
    const float* lc2_b = (const float*)d_in[10];
    const float* Wq  = (const float*)d_in[11];
    const float* Wk  = (const float*)d_in[12];
    const float* Wv  = (const float*)d_in[13];
    const float* Wo  = (const float*)d_in[14];
    const float* Wf1 = (const float*)d_in[15];
    const float* Wf2 = (const float*)d_in[16];
    const int* src = edge_index;
    const int* dst = edge_index + N_EDGES;

    float *p_x, *p_e, *p_msg, *p_agg, *p_h, *p_zin, *p_zg, *p_q, *p_k, *p_v,
          *p_ao, *p_x1, *p_ffn, *p_x2, *p_y;
    uint32_t *whi, *wlo;
    cudaGetSymbolAddress((void**)&p_x,   g_x);
    cudaGetSymbolAddress((void**)&p_e,   g_e);
    cudaGetSymbolAddress((void**)&p_msg, g_msg);
    cudaGetSymbolAddress((void**)&p_agg, g_agg);
    cudaGetSymbolAddress((void**)&p_h,   g_h);
    cudaGetSymbolAddress((void**)&p_zin, g_zin);
    cudaGetSymbolAddress((void**)&p_zg,  g_zg);
    cudaGetSymbolAddress((void**)&p_q,   g_q);
    cudaGetSymbolAddress((void**)&p_k,   g_k);
    cudaGetSymbolAddress((void**)&p_v,   g_v);
    cudaGetSymbolAddress((void**)&p_ao,  g_ao);
    cudaGetSymbolAddress((void**)&p_x1,  g_x1);
    cudaGetSymbolAddress((void**)&p_ffn, g_ffn);
    cudaGetSymbolAddress((void**)&p_x2,  g_x2);
    cudaGetSymbolAddress((void**)&p_y,   g_y);
    cudaGetSymbolAddress((void**)&whi,   g_whi);
    cudaGetSymbolAddress((void**)&wlo,   g_wlo);

    const int SM128 = 2 * 128 * 32 * 4 + 2 * 128 * 32 * 4;   // 64KB
    const int SM64  = 2 * 128 * 32 * 4 + 2 * 64 * 32 * 4;    // 48KB
    const int SMFLM = (8192 + 2 * 8192) * 4;                 // 96KB
    cudaFuncSetAttribute(tgemm<128, 1, false, true, true>,  cudaFuncAttributeMaxDynamicSharedMemorySize, SM128);
    cudaFuncSetAttribute(tgemm<128, 1, false, true, false>, cudaFuncAttributeMaxDynamicSharedMemorySize, SM128);
    cudaFuncSetAttribute(tgemm<128, 0, true, false, false>, cudaFuncAttributeMaxDynamicSharedMemorySize, SM128);
    cudaFuncSetAttribute(tgemm<128, 0, false, false, false>,cudaFuncAttributeMaxDynamicSharedMemorySize, SM128);
    cudaFuncSetAttribute(tgemm<128, 0, false, true, false>, cudaFuncAttributeMaxDynamicSharedMemorySize, SM128);
    cudaFuncSetAttribute(tgemm<128, 2, false, false, false>,cudaFuncAttributeMaxDynamicSharedMemorySize, SM128);
    cudaFuncSetAttribute(tgemm<64, 0, true, false, false>,  cudaFuncAttributeMaxDynamicSharedMemorySize, SM64);
    cudaFuncSetAttribute(flm, cudaFuncAttributeMaxDynamicSharedMemorySize, SMFLM);

    // output layout: probs-only, or labels(16384) ++ probs
    float* out = (float*)d_out;
    const long long PROBS_N = (long long)NROWS * VOCAB;
    float* labels_out = nullptr;
    float* probs = out;
    if ((long long)out_size >= PROBS_N + NROWS) { labels_out = out; probs = out + NROWS; }

    // 1) fused labels+edge-embed, node embed, weight presplit
    k_lab_embed_e<<<(NROWS * 16) / 256, 256>>>(edge_tokens, mask_rows, emb, labels_out, p_e);
    k_embed<<<(N_NODES * L_TOK * 16) / 256, 256>>>(node_tokens, emb, p_x, N_NODES * L_TOK * 16);
    k_prep<<<(TOTAL_PAIRS + 255) / 256, 256>>>(W_msg, W_node, lc1_w, Wq, Wk, Wv, Wo, Wf1, Wf2, lc2_w, emb);

    // 2) GNN  (W_msg GEMM lands in ncu's profiled slot)
    tgemm<128, 1, false, true, true><<<dim3(FD / 128, N_EDGES / 128), 256, SM128>>>(
        p_e, whi + OFF_WMSG, wlo + OFF_WMSG, nullptr, p_x, src, p_msg, N_EDGES, FD, FD);
    k_zero<<<(N_NODES * FD / 4) / 256, 256>>>(p_agg, N_NODES * FD / 4);
    k_scatter<<<(N_EDGES * FD) / 256, 256>>>(p_msg, dst, p_agg);
    tgemm<128, 1, false, true, false><<<dim3(FD / 128, N_NODES / 128), 256, SM128>>>(
        p_x, whi + OFF_WNODE, wlo + OFF_WNODE, nullptr, p_agg, nullptr, p_h, N_NODES, FD, FD);

    // 3) eh gather + lc1
    k_zin<<<(NROWS * 16) / 256, 256>>>(p_h, src, dst, p_zin);
    tgemm<128, 0, true, false, false><<<dim3(DG / 128, NROWS / 128), 256, SM128>>>(
        p_zin, whi + OFF_LC1, wlo + OFF_LC1, lc1_b, nullptr, nullptr, p_zg, NROWS, DG, D_EMB);

    // 4) transformer block
    tgemm<128, 0, false, false, false><<<dim3(DG / 128, NROWS / 128), 256, SM128>>>(
        p_zg, whi + OFF_WQ, wlo + OFF_WQ, nullptr, nullptr, nullptr, p_q, NROWS, DG, DG);
    tgemm<128, 0, false, false, false><<<dim3(DG / 128, NROWS / 128), 256, SM128>>>(
        p_zg, whi + OFF_WK, wlo + OFF_WK, nullptr, nullptr, nullptr, p_k, NROWS, DG, DG);
    tgemm<128, 0, false, false, false><<<dim3(DG / 128, NROWS / 128), 256, SM128>>>(
        p_zg, whi + OFF_WV, wlo + OFF_WV, nullptr, nullptr, nullptr, p_v, NROWS, DG, DG);
    k_attn<<<N_EDGES, 256>>>(p_q, p_k, p_v, p_ao);
    tgemm<128, 0, false, true, false><<<dim3(DG / 128, NROWS / 128), 256, SM128>>>(
        p_ao, whi + OFF_WO, wlo + OFF_WO, nullptr, p_zg, nullptr, p_x1, NROWS, DG, DG);
    tgemm<128, 2, false, false, false><<<dim3(4 * DG / 128, NROWS / 128), 256, SM128>>>(
        p_x1, whi + OFF_WF1, wlo + OFF_WF1, nullptr, nullptr, nullptr, p_ffn, NROWS, 4 * DG, DG);
    tgemm<128, 0, false, true, false><<<dim3(DG / 128, NROWS / 128), 256, SM128>>>(
        p_ffn, whi + OFF_WF2, wlo + OFF_WF2, nullptr, p_x1, nullptr, p_x2, NROWS, DG, 4 * DG);

    // 5) lc2
    tgemm<64, 0, true, false, false><<<dim3(1, NROWS / 128), 256, SM64>>>(
        p_x2, whi + OFF_LC2, wlo + OFF_LC2, lc2_b, nullptr, nullptr, p_y, NROWS, D_EMB, DG);

    // 6) fused tied lm head + softmax
    flm<<<NROWS / 128, 256, SMFLM>>>(p_y, whi + OFF_EMB, wlo + OFF_EMB, probs);
}

// round 7
// speedup vs baseline: 2.5059x; 1.2101x over previous
#include <cuda_runtime.h>
#include <cuda_bf16.h>
#include <math.h>
#include <stdint.h>

// ---------------- problem constants ----------------
#define N_NODES 8192
#define N_EDGES 2048
#define L_TOK   8
#define D_EMB   64
#define FD      512
#define DG      256
#define NH      4
#define HD      64
#define VOCAB   10000
#define NROWS   (N_EDGES * L_TOK)   // 16384
#define NVT     157                  // ceil(VOCAB/64) vocab tiles

// ---------------- scratch ----------------
__device__ float g_x  [N_NODES * FD];
__device__ float g_e  [N_EDGES * FD];
__device__ float g_msg[N_EDGES * FD];
__device__ float g_agg[N_NODES * FD];
__device__ float g_h  [N_NODES * FD];
__device__ float g_zin[NROWS * D_EMB];
__device__ float g_zg [NROWS * DG];
__device__ float g_q  [NROWS * DG];
__device__ float g_k  [NROWS * DG];
__device__ float g_v  [NROWS * DG];
__device__ float g_ao [NROWS * DG];
__device__ float g_x1 [NROWS * DG];
__device__ float g_ffn[NROWS * 4 * DG];
__device__ float g_x2 [NROWS * DG];
__device__ float g_y  [NROWS * D_EMB];
__device__ float2 g_pstat[NVT * NROWS];
__device__ float g_Ms[NROWS];
__device__ float g_Is[NROWS];

// pre-split weight planes (packed bf16x2: word = {bf16(k), bf16(k+1)})
#define OFF_WMSG  0
#define OFF_WNODE (OFF_WMSG  + 256*512)
#define OFF_LC1   (OFF_WNODE + 256*512)
#define OFF_WQ    (OFF_LC1   + 32*256)
#define OFF_WK    (OFF_WQ    + 128*256)
#define OFF_WV    (OFF_WK    + 128*256)
#define OFF_WO    (OFF_WV    + 128*256)
#define OFF_WF1   (OFF_WO    + 128*256)
#define OFF_WF2   (OFF_WF1   + 128*1024)
#define OFF_LC2   (OFF_WF2   + 512*256)
#define OFF_EMB   (OFF_LC2   + 128*64)
#define TOTAL_PAIRS (OFF_EMB + VOCAB*32)
__device__ uint32_t g_whi[TOTAL_PAIRS];
__device__ uint32_t g_wlo[TOTAL_PAIRS];

// ---------------- helpers ----------------
__device__ __forceinline__ void splitpair(float x0, float x1, uint32_t& hi, uint32_t& lo) {
    __nv_bfloat162 h = __floats2bfloat162_rn(x0, x1);
    float h0 = __bfloat162float(h.x), h1 = __bfloat162float(h.y);
    __nv_bfloat162 l = __floats2bfloat162_rn(x0 - h0, x1 - h1);
    hi = *reinterpret_cast<uint32_t*>(&h);
    lo = *reinterpret_cast<uint32_t*>(&l);
}

__device__ __forceinline__ void mma16(float* c,
    uint32_t a0, uint32_t a1, uint32_t a2, uint32_t a3, uint32_t b0, uint32_t b1)
{
    asm volatile(
        "mma.sync.aligned.m16n8k16.row.col.f32.bf16.bf16.f32 "
        "{%0,%1,%2,%3},{%4,%5,%6,%7},{%8,%9},{%0,%1,%2,%3};"
        : "+f"(c[0]), "+f"(c[1]), "+f"(c[2]), "+f"(c[3])
        : "r"(a0), "r"(a1), "r"(a2), "r"(a3), "r"(b0), "r"(b1));
}

__device__ __forceinline__ float gelu_f(float v) {
    float u = 0.7978845608028654f * (v + 0.044715f * v * v * v);
    float t;
    asm("tanh.approx.f32 %0, %1;" : "=f"(t) : "f"(u));
    return 0.5f * v * (1.f + t);
}

__device__ __forceinline__ void upd_stats(float& m, float& s, float x) {
    if (x > m) { s = s * __expf(m - x) + 1.f; m = x; }
    else       { s += __expf(x - m); }
}

// XOR swizzle: octet lanes get distinct bank columns
__device__ __forceinline__ int swz(int slot, int rc, int DIM) {
    return slot * DIM + (rc ^ ((slot & 3) << 1));
}

// ---------------- small kernels ----------------
__global__ void k_lab_embed_e(const int* __restrict__ etok, const int* __restrict__ maskbits,
                              const float* __restrict__ emb, float* __restrict__ labels_out,
                              float* __restrict__ oute)
{
    int i = blockIdx.x * blockDim.x + threadIdx.x;
    if (i >= NROWS * 16) return;
    int slot = i >> 4, d4 = i & 15;
    int e = slot >> 3;
    int tok = etok[slot];
    bool masked = (maskbits[e] != 0) && (tok > 3);
    int mtok = masked ? 4 : tok;
    if (d4 == 0 && labels_out) labels_out[slot] = masked ? (float)tok : -100.0f;
    ((float4*)oute)[i] = ((const float4*)emb)[mtok * 16 + d4];
}

__global__ void k_embed(const int* __restrict__ toks, const float* __restrict__ emb,
                        float* __restrict__ out, int total_f4)
{
    int i = blockIdx.x * blockDim.x + threadIdx.x;
    if (i >= total_f4) return;
    int slot = i >> 4, d4 = i & 15;
    ((float4*)out)[i] = ((const float4*)emb)[toks[slot] * 16 + d4];
}

__device__ __forceinline__ void prep_k(const float* __restrict__ W, int N, int il, int base) {
    int kp = il / N, n = il - kp * N;
    uint32_t hi, lo;
    splitpair(W[(2 * kp) * N + n], W[(2 * kp + 1) * N + n], hi, lo);
    g_whi[base + il] = hi; g_wlo[base + il] = lo;
}

__global__ void k_prep(const float* __restrict__ Wmsg, const float* __restrict__ Wnode,
                       const float* __restrict__ lc1, const float* __restrict__ Wq,
                       const float* __restrict__ Wk, const float* __restrict__ Wv,
                       const float* __restrict__ Wo, const float* __restrict__ Wf1,
                       const float* __restrict__ Wf2, const float* __restrict__ lc2,
                       const float* __restrict__ emb)
{
    int i = blockIdx.x * blockDim.x + threadIdx.x;
    if (i >= TOTAL_PAIRS) return;
    if      (i < OFF_WNODE) prep_k(Wmsg,  512,  i - OFF_WMSG,  OFF_WMSG);
    else if (i < OFF_LC1)   prep_k(Wnode, 512,  i - OFF_WNODE, OFF_WNODE);
    else if (i < OFF_WQ)    prep_k(lc1,   256,  i - OFF_LC1,   OFF_LC1);
    else if (i < OFF_WK)    prep_k(Wq,    256,  i - OFF_WQ,    OFF_WQ);
    else if (i < OFF_WV)    prep_k(Wk,    256,  i - OFF_WK,    OFF_WK);
    else if (i < OFF_WO)    prep_k(Wv,    256,  i - OFF_WV,    OFF_WV);
    else if (i < OFF_WF1)   prep_k(Wo,    256,  i - OFF_WO,    OFF_WO);
    else if (i < OFF_WF2)   prep_k(Wf1,   1024, i - OFF_WF1,   OFF_WF1);
    else if (i < OFF_LC2)   prep_k(Wf2,   256,  i - OFF_WF2,   OFF_WF2);
    else if (i < OFF_EMB)   prep_k(lc2,   64,   i - OFF_LC2,   OFF_LC2);
    else {
        // emb planes k-major: [kp][VOCAB]
        int il = i - OFF_EMB;
        int kp = il / VOCAB, n = il - kp * VOCAB;
        uint32_t hi, lo;
        splitpair(emb[n * 64 + 2 * kp], emb[n * 64 + 2 * kp + 1], hi, lo);
        g_whi[i] = hi; g_wlo[i] = lo;
    }
}

__global__ void k_zero(float* __restrict__ p, int total_f4)
{
    int i = blockIdx.x * blockDim.x + threadIdx.x;
    if (i < total_f4) ((float4*)p)[i] = make_float4(0.f, 0.f, 0.f, 0.f);
}

__global__ void k_scatter(const float* __restrict__ msg, const int* __restrict__ dst,
                          float* __restrict__ agg)
{
    int t = blockIdx.x * blockDim.x + threadIdx.x;
    if (t >= N_EDGES * FD) return;
    int e = t >> 9, c = t & 511;
    atomicAdd(&agg[dst[e] * FD + c], msg[t]);
}

__global__ void k_zin(const float* __restrict__ h, const int* __restrict__ src,
                      const int* __restrict__ dst, float* __restrict__ zin)
{
    int i = blockIdx.x * blockDim.x + threadIdx.x;
    if (i >= NROWS * 16) return;
    int r = i >> 4, d4 = i & 15;
    int e = r >> 3, l = r & 7;
    const float4* h4 = (const float4*)h;
    float4 a = h4[src[e] * 128 + l * 16 + d4];
    float4 b = h4[dst[e] * 128 + l * 16 + d4];
    ((float4*)zin)[i] = make_float4(a.x + b.x, a.y + b.y, a.z + b.z, a.w + b.w);
}

// ---------------- bf16-split tensor GEMM: BM=128, BN=64, BK=32, 2 CTAs/SM ----------------
template<int ACT, bool HAS_BIAS, bool HAS_ADD, bool ADD_IDX>
__global__ void __launch_bounds__(256, 2)
tgemm(const float* __restrict__ A,
      const uint32_t* __restrict__ Bhi, const uint32_t* __restrict__ Blo,
      const float* __restrict__ bias, const float* __restrict__ Add,
      const int* __restrict__ addIdx, float* __restrict__ C,
      int M, int N, int K)
{
    constexpr int BM = 128, BN = 64;
    constexpr int WN = 16, MT = 4, NT = 2;
    constexpr int KC = 8, JP = 4;

    extern __shared__ uint32_t dynsm[];
    uint32_t* AsW[2] = { dynsm, dynsm + BM * 32 };
    uint32_t* BsW[2] = { dynsm + 2 * BM * 32, dynsm + 2 * BM * 32 + BN * 32 };

    int tid = threadIdx.x, lane = tid & 31, w = tid >> 5;
    int g = lane >> 2, tg = lane & 3;
    int wM = w >> 2, wN = w & 3;
    int m0 = blockIdx.y * BM, n0 = blockIdx.x * BN;

    float acc[MT][NT][4];
#pragma unroll
    for (int mt = 0; mt < MT; mt++)
#pragma unroll
        for (int nt = 0; nt < NT; nt++)
#pragma unroll
            for (int c = 0; c < 4; c++) acc[mt][nt][c] = 0.f;

    int arow = tid >> 1, ahalf = tid & 1;
    int bn = tid % BN, bq = tid / BN, kb = bq * KC;

    float sa[16];
    uint32_t hw[JP], lw[JP];

    auto ldA = [&](int k0) {
        const float* p = A + (size_t)(m0 + arow) * K + k0 + ahalf * 16;
#pragma unroll
        for (int j = 0; j < 16; j += 4) *(float4*)&sa[j] = *(const float4*)(p + j);
    };
    auto ldB = [&](int k0) {
        int kp0 = (k0 + kb) >> 1;
#pragma unroll
        for (int jp = 0; jp < JP; jp++) {
            size_t idx = (size_t)(kp0 + jp) * N + n0 + bn;
            hw[jp] = Bhi[idx]; lw[jp] = Blo[idx];
        }
    };
    auto stA = [&](int buf) {
#pragma unroll
        for (int j = 0; j < 16; j += 2) {
            int p = (ahalf * 16 + j) >> 1, s = p >> 3, lp = p & 7, t = lp & 3;
            int off = (lp & 4) ? 2 : 0;
            uint32_t hi, lo; splitpair(sa[j], sa[j + 1], hi, lo);
            *(uint2*)&AsW[buf][swz((s << 2) | t, arow, BM) * 4 + off] = make_uint2(hi, lo);
        }
    };
    auto stB = [&](int buf) {
#pragma unroll
        for (int jp = 0; jp < JP; jp++) {
            int p = (kb >> 1) + jp, s = p >> 3, lp = p & 7, t = lp & 3;
            int off = (lp & 4) ? 2 : 0;
            *(uint2*)&BsW[buf][swz((s << 2) | t, bn, BN) * 4 + off] = make_uint2(hw[jp], lw[jp]);
        }
    };

    int KT = K / 32;
    ldA(0); ldB(0); stA(0); stB(0);
    __syncthreads();
    for (int kt = 0; kt < KT; kt++) {
        int cur = kt & 1;
        if (kt + 1 < KT) { ldA((kt + 1) * 32); ldB((kt + 1) * 32); }
        const uint4* A4 = (const uint4*)AsW[cur];
        const uint4* B4 = (const uint4*)BsW[cur];
#pragma unroll
        for (int s = 0; s < 2; s++) {
            uint4 af[MT][2], bf[NT];
#pragma unroll
            for (int mt = 0; mt < MT; mt++) {
                int mr = wM * 64 + mt * 16 + g;
                af[mt][0] = A4[swz(s * 4 + tg, mr, BM)];
                af[mt][1] = A4[swz(s * 4 + tg, mr + 8, BM)];
            }
#pragma unroll
            for (int nt = 0; nt < NT; nt++)
                bf[nt] = B4[swz(s * 4 + tg, wN * WN + nt * 8 + g, BN)];
#pragma unroll
            for (int mt = 0; mt < MT; mt++)
#pragma unroll
                for (int nt = 0; nt < NT; nt++) {
                    mma16(acc[mt][nt], af[mt][0].x, af[mt][1].x, af[mt][0].z, af[mt][1].z,
                          bf[nt].x, bf[nt].z);
                    mma16(acc[mt][nt], af[mt][0].x, af[mt][1].x, af[mt][0].z, af[mt][1].z,
                          bf[nt].y, bf[nt].w);
                    mma16(acc[mt][nt], af[mt][0].y, af[mt][1].y, af[mt][0].w, af[mt][1].w,
                          bf[nt].x, bf[nt].z);
                }
        }
        if (kt + 1 < KT) { stA((kt + 1) & 1); stB((kt + 1) & 1); }
        __syncthreads();
    }

#pragma unroll
    for (int mt = 0; mt < MT; mt++) {
        int r1 = m0 + wM * 64 + mt * 16 + g;
        int r2 = r1 + 8;
        int a1 = r1, a2 = r2;
        if (HAS_ADD && ADD_IDX) { a1 = addIdx[r1]; a2 = addIdx[r2]; }
#pragma unroll
        for (int nt = 0; nt < NT; nt++) {
            int cb = n0 + wN * WN + nt * 8 + 2 * tg;
            float e0 = acc[mt][nt][0], e1 = acc[mt][nt][1];
            float e2 = acc[mt][nt][2], e3 = acc[mt][nt][3];
            if (HAS_BIAS) { float b0 = bias[cb], b1 = bias[cb + 1]; e0 += b0; e1 += b1; e2 += b0; e3 += b1; }
            if (HAS_ADD) {
                e0 += Add[(size_t)a1 * N + cb]; e1 += Add[(size_t)a1 * N + cb + 1];
                e2 += Add[(size_t)a2 * N + cb]; e3 += Add[(size_t)a2 * N + cb + 1];
            }
            if (ACT == 1) { e0 = fmaxf(e0, 0.f); e1 = fmaxf(e1, 0.f); e2 = fmaxf(e2, 0.f); e3 = fmaxf(e3, 0.f); }
            if (ACT == 2) { e0 = gelu_f(e0); e1 = gelu_f(e1); e2 = gelu_f(e2); e3 = gelu_f(e3); }
            *(float2*)(C + (size_t)r1 * N + cb) = make_float2(e0, e1);
            *(float2*)(C + (size_t)r2 * N + cb) = make_float2(e2, e3);
        }
    }
}

// ---------------- lm_head GEMM + partial softmax stats ----------------
// grid (NVT, NROWS/128). logits written to probs buffer; per-(tile,row) stats.
__global__ void __launch_bounds__(256, 2)
lmg(const float* __restrict__ Y,
    const uint32_t* __restrict__ Bhi, const uint32_t* __restrict__ Blo,
    float* __restrict__ logits, float2* __restrict__ pstat)
{
    constexpr int BM = 128, BN = 64;
    constexpr int WN = 16, MT = 4, NT = 2;
    constexpr int KC = 8, JP = 4;
    const int N = VOCAB, K = 64;

    extern __shared__ uint32_t dynsm[];
    uint32_t* AsW[2] = { dynsm, dynsm + BM * 32 };
    uint32_t* BsW[2] = { dynsm + 2 * BM * 32, dynsm + 2 * BM * 32 + BN * 32 };
    __shared__ float2 red[4][BM];

    int tid = threadIdx.x, lane = tid & 31, w = tid >> 5;
    int g = lane >> 2, tg = lane & 3;
    int wM = w >> 2, wN = w & 3;
    int m0 = blockIdx.y * BM, n0 = blockIdx.x * BN;

    float acc[MT][NT][4];
#pragma unroll
    for (int mt = 0; mt < MT; mt++)
#pragma unroll
        for (int nt = 0; nt < NT; nt++)
#pragma unroll
            for (int c = 0; c < 4; c++) acc[mt][nt][c] = 0.f;

    int arow = tid >> 1, ahalf = tid & 1;
    int bn = tid % BN, bq = tid / BN, kb = bq * KC;
    int bcol = n0 + bn;

    float sa[16];
    uint32_t hw[JP], lw[JP];

    auto ldA = [&](int k0) {
        const float* p = Y + (size_t)(m0 + arow) * K + k0 + ahalf * 16;
#pragma unroll
        for (int j = 0; j < 16; j += 4) *(float4*)&sa[j] = *(const float4*)(p + j);
    };
    auto ldB = [&](int k0) {
        int kp0 = (k0 + kb) >> 1;
        if (bcol < N) {
#pragma unroll
            for (int jp = 0; jp < JP; jp++) {
                size_t idx = (size_t)(kp0 + jp) * N + bcol;
                hw[jp] = Bhi[idx]; lw[jp] = Blo[idx];
            }
        } else {
#pragma unroll
            for (int jp = 0; jp < JP; jp++) { hw[jp] = 0; lw[jp] = 0; }
        }
    };
    auto stA = [&](int buf) {
#pragma unroll
        for (int j = 0; j < 16; j += 2) {
            int p = (ahalf * 16 + j) >> 1, s = p >> 3, lp = p & 7, t = lp & 3;
            int off = (lp & 4) ? 2 : 0;
            uint32_t hi, lo; splitpair(sa[j], sa[j + 1], hi, lo);
            *(uint2*)&AsW[buf][swz((s << 2) | t, arow, BM) * 4 + off] = make_uint2(hi, lo);
        }
    };
    auto stB = [&](int buf) {
#pragma unroll
        for (int jp = 0; jp < JP; jp++) {
            int p = (kb >> 1) + jp, s = p >> 3, lp = p & 7, t = lp & 3;
            int off = (lp & 4) ? 2 : 0;
            *(uint2*)&BsW[buf][swz((s << 2) | t, bn, BN) * 4 + off] = make_uint2(hw[jp], lw[jp]);
        }
    };

    ldA(0); ldB(0); stA(0); stB(0);
    __syncthreads();
#pragma unroll
    for (int kt = 0; kt < 2; kt++) {
        int cur = kt & 1;
        if (kt == 0) { ldA(32); ldB(32); }
        const uint4* A4 = (const uint4*)AsW[cur];
        const uint4* B4 = (const uint4*)BsW[cur];
#pragma unroll
        for (int s = 0; s < 2; s++) {
            uint4 af[MT][2], bf[NT];
#pragma unroll
            for (int mt = 0; mt < MT; mt++) {
                int mr = wM * 64 + mt * 16 + g;
                af[mt][0] = A4[swz(s * 4 + tg, mr, BM)];
                af[mt][1] = A4[swz(s * 4 + tg, mr + 8, BM)];
            }
#pragma unroll
            for (int nt = 0; nt < NT; nt++)
                bf[nt] = B4[swz(s * 4 + tg, wN * WN + nt * 8 + g, BN)];
#pragma unroll
            for (int mt = 0; mt < MT; mt++)
#pragma unroll
                for (int nt = 0; nt < NT; nt++) {
                    mma16(acc[mt][nt], af[mt][0].x, af[mt][1].x, af[mt][0].z, af[mt][1].z,
                          bf[nt].x, bf[nt].z);
                    mma16(acc[mt][nt], af[mt][0].x, af[mt][1].x, af[mt][0].z, af[mt][1].z,
                          bf[nt].y, bf[nt].w);
                    mma16(acc[mt][nt], af[mt][0].y, af[mt][1].y, af[mt][0].w, af[mt][1].w,
                          bf[nt].x, bf[nt].z);
                }
        }
        if (kt == 0) { stA(1); stB(1); }
        __syncthreads();
    }

    // epilogue: write logits + per-thread stats
    float mreg[8], sreg[8];
#pragma unroll
    for (int i = 0; i < 8; i++) { mreg[i] = -1e30f; sreg[i] = 0.f; }

#pragma unroll
    for (int mt = 0; mt < MT; mt++) {
        int r1 = m0 + wM * 64 + mt * 16 + g, r2 = r1 + 8;
#pragma unroll
        for (int nt = 0; nt < NT; nt++) {
            int cb = n0 + wN * WN + nt * 8 + 2 * tg;
            if (cb < N) {
                float e0 = acc[mt][nt][0], e1 = acc[mt][nt][1];
                float e2 = acc[mt][nt][2], e3 = acc[mt][nt][3];
                *(float2*)(logits + (size_t)r1 * N + cb) = make_float2(e0, e1);
                *(float2*)(logits + (size_t)r2 * N + cb) = make_float2(e2, e3);
                upd_stats(mreg[mt * 2], sreg[mt * 2], e0);
                upd_stats(mreg[mt * 2], sreg[mt * 2], e1);
                upd_stats(mreg[mt * 2 + 1], sreg[mt * 2 + 1], e2);
                upd_stats(mreg[mt * 2 + 1], sreg[mt * 2 + 1], e3);
            }
        }
    }
    // quad reduce (tg)
#pragma unroll
    for (int i = 0; i < 8; i++) {
#pragma unroll
        for (int d = 1; d < 4; d <<= 1) {
            float om = __shfl_xor_sync(0xffffffffu, mreg[i], d);
            float os = __shfl_xor_sync(0xffffffffu, sreg[i], d);
            float M = fmaxf(mreg[i], om);
            sreg[i] = sreg[i] * __expf(mreg[i] - M) + os * __expf(om - M);
            mreg[i] = M;
        }
    }
    if (tg == 0) {
#pragma unroll
        for (int mt = 0; mt < MT; mt++)
#pragma unroll
            for (int h = 0; h < 2; h++)
                red[wN][wM * 64 + mt * 16 + h * 8 + g] =
                    make_float2(mreg[mt * 2 + h], sreg[mt * 2 + h]);
    }
    __syncthreads();
    if (tid < BM) {
        float M = -1e30f, S = 0.f;
#pragma unroll
        for (int j = 0; j < 4; j++) {
            float2 r = red[j][tid];
            float nM = fmaxf(M, r.x);
            S = S * __expf(M - nM) + r.y * __expf(r.x - nM);
            M = nM;
        }
        pstat[(size_t)blockIdx.x * NROWS + m0 + tid] = make_float2(M, S);
    }
}

// combine partial stats across vocab tiles
__global__ void k_red()
{
    int r = blockIdx.x * 256 + threadIdx.x;
    if (r >= NROWS) return;
    float M = -1e30f, S = 0.f;
    for (int t = 0; t < NVT; t++) {
        float2 p = g_pstat[(size_t)t * NROWS + r];
        float nM = fmaxf(M, p.x);
        S = S * __expf(M - nM) + p.y * __expf(p.x - nM);
        M = nM;
    }
    g_Ms[r] = M;
    g_Is[r] = 1.f / S;
}

// normalize logits -> probs in place
__global__ void __launch_bounds__(256)
k_norm(float* __restrict__ probs)
{
    int row = blockIdx.x, tid = threadIdx.x;
    float M = g_Ms[row], I = g_Is[row];
    float4* p = (float4*)(probs + (size_t)row * VOCAB);
#pragma unroll
    for (int r = 0; r < 10; r++) {
        int i = tid + r * 256;
        if (i < VOCAB / 4) {
            float4 q = p[i];
            q.x = __expf(q.x - M) * I;
            q.y = __expf(q.y - M) * I;
            q.z = __expf(q.z - M) * I;
            q.w = __expf(q.w - M) * I;
            p[i] = q;
        }
    }
}

// ---------------- attention ----------------
__global__ void __launch_bounds__(256)
k_attn(const float* __restrict__ Q, const float* __restrict__ Km,
       const float* __restrict__ V, float* __restrict__ O)
{
    int e = blockIdx.x;
    int tid = threadIdx.x;
    __shared__ float qs[8][DG], ks[8][DG], vs[8][DG];
    __shared__ float att[NH][8][8];

    for (int i = tid; i < 8 * DG; i += 256) {
        int s = i >> 8, c = i & 255;
        size_t base = (size_t)(e * 8 + s) * DG + c;
        qs[s][c] = Q[base]; ks[s][c] = Km[base]; vs[s][c] = V[base];
    }
    __syncthreads();
    {
        int h = tid >> 6, rem = tid & 63, qi = rem >> 3, ki = rem & 7;
        float acc = 0.f;
#pragma unroll
        for (int d = 0; d < HD; d++) acc = fmaf(qs[qi][h * HD + d], ks[ki][h * HD + d], acc);
        att[h][qi][ki] = acc * 0.125f;
    }
    __syncthreads();
    if (tid < 32) {
        int h = tid >> 3, qi = tid & 7;
        float m = -1e30f;
#pragma unroll
        for (int ki = 0; ki < 8; ki++) m = fmaxf(m, att[h][qi][ki]);
        float s = 0.f, ex[8];
#pragma unroll
        for (int ki = 0; ki < 8; ki++) { ex[ki] = __expf(att[h][qi][ki] - m); s += ex[ki]; }
        float inv = 1.f / s;
#pragma unroll
        for (int ki = 0; ki < 8; ki++) att[h][qi][ki] = ex[ki] * inv;
    }
    __syncthreads();
    {
        int c = tid, h = c >> 6;
#pragma unroll
        for (int s = 0; s < 8; s++) {
            float acc = 0.f;
#pragma unroll
            for (int ki = 0; ki < 8; ki++) acc = fmaf(att[h][s][ki], vs[ki][c], acc);
            O[(size_t)(e * 8 + s) * DG + c] = acc;
        }
    }
}

// ---------------- host launcher ----------------
extern "C" void kernel_launch(void* const* d_in, const int* in_sizes, int n_in,
                              void* d_out, int out_size)
{
    const int*   node_tokens = (const int*)d_in[0];
    const int*   edge_tokens = (const int*)d_in[1];
    const int*   edge_index  = (const int*)d_in[2];
    const int*   mask_rows   = (const int*)d_in[3];
    const float* emb   = (const float*)d_in[4];
    const float* W_msg = (const float*)d_in[5];
    const float* W_node= (const float*)d_in[6];
    const float* lc1_w = (const float*)d_in[7];
    const float* lc1_b = (const float*)d_in[8];
    const float* lc2_w = (const float*)d_in[9];
    const float* lc2_b = (const float*)d_in[10];
    const float* Wq  = (const float*)d_in[11];
    const float* Wk  = (const float*)d_in[12];
    const float* Wv  = (const float*)d_in[13];
    const float* Wo  = (const float*)d_in[14];
    const float* Wf1 = (const float*)d_in[15];
    const float* Wf2 = (const float*)d_in[16];
    const int* src = edge_index;
    const int* dst = edge_index + N_EDGES;

    float *p_x, *p_e, *p_msg, *p_agg, *p_h, *p_zin, *p_zg, *p_q, *p_k, *p_v,
          *p_ao, *p_x1, *p_ffn, *p_x2, *p_y;
    float2* p_pstat;
    uint32_t *whi, *wlo;
    cudaGetSymbolAddress((void**)&p_x,   g_x);
    cudaGetSymbolAddress((void**)&p_e,   g_e);
    cudaGetSymbolAddress((void**)&p_msg, g_msg);
    cudaGetSymbolAddress((void**)&p_agg, g_agg);
    cudaGetSymbolAddress((void**)&p_h,   g_h);
    cudaGetSymbolAddress((void**)&p_zin, g_zin);
    cudaGetSymbolAddress((void**)&p_zg,  g_zg);
    cudaGetSymbolAddress((void**)&p_q,   g_q);
    cudaGetSymbolAddress((void**)&p_k,   g_k);
    cudaGetSymbolAddress((void**)&p_v,   g_v);
    cudaGetSymbolAddress((void**)&p_ao,  g_ao);
    cudaGetSymbolAddress((void**)&p_x1,  g_x1);
    cudaGetSymbolAddress((void**)&p_ffn, g_ffn);
    cudaGetSymbolAddress((void**)&p_x2,  g_x2);
    cudaGetSymbolAddress((void**)&p_y,   g_y);
    cudaGetSymbolAddress((void**)&p_pstat, g_pstat);
    cudaGetSymbolAddress((void**)&whi,   g_whi);
    cudaGetSymbolAddress((void**)&wlo,   g_wlo);

    const int SMG = (2 * 128 * 32 + 2 * 64 * 32) * 4;   // 48KB
    cudaFuncSetAttribute(tgemm<1, false, true, true>,   cudaFuncAttributeMaxDynamicSharedMemorySize, SMG);
    cudaFuncSetAttribute(tgemm<1, false, true, false>,  cudaFuncAttributeMaxDynamicSharedMemorySize, SMG);
    cudaFuncSetAttribute(tgemm<0, true, false, false>,  cudaFuncAttributeMaxDynamicSharedMemorySize, SMG);
    cudaFuncSetAttribute(tgemm<0, false, false, false>, cudaFuncAttributeMaxDynamicSharedMemorySize, SMG);
    cudaFuncSetAttribute(tgemm<0, false, true, false>,  cudaFuncAttributeMaxDynamicSharedMemorySize, SMG);
    cudaFuncSetAttribute(tgemm<2, false, false, false>, cudaFuncAttributeMaxDynamicSharedMemorySize, SMG);
    cudaFuncSetAttribute(lmg, cudaFuncAttributeMaxDynamicSharedMemorySize, SMG);

    // output layout: probs-only, or labels(16384) ++ probs
    float* out = (float*)d_out;
    const long long PROBS_N = (long long)NROWS * VOCAB;
    float* labels_out = nullptr;
    float* probs = out;
    if ((long long)out_size >= PROBS_N + NROWS) { labels_out = out; probs = out + NROWS; }

    // 1) fused labels+edge-embed, node embed, weight presplit
    k_lab_embed_e<<<(NROWS * 16) / 256, 256>>>(edge_tokens, mask_rows, emb, labels_out, p_e);
    k_embed<<<(N_NODES * L_TOK * 16) / 256, 256>>>(node_tokens, emb, p_x, N_NODES * L_TOK * 16);
    k_prep<<<(TOTAL_PAIRS + 255) / 256, 256>>>(W_msg, W_node, lc1_w, Wq, Wk, Wv, Wo, Wf1, Wf2, lc2_w, emb);

    // 2) GNN
    tgemm<1, false, true, true><<<dim3(FD / 64, N_EDGES / 128), 256, SMG>>>(
        p_e, whi + OFF_WMSG, wlo + OFF_WMSG, nullptr, p_x, src, p_msg, N_EDGES, FD, FD);
    k_zero<<<(N_NODES * FD / 4) / 256, 256>>>(p_agg, N_NODES * FD / 4);
    k_scatter<<<(N_EDGES * FD) / 256, 256>>>(p_msg, dst, p_agg);
    tgemm<1, false, true, false><<<dim3(FD / 64, N_NODES / 128), 256, SMG>>>(
        p_x, whi + OFF_WNODE, wlo + OFF_WNODE, nullptr, p_agg, nullptr, p_h, N_NODES, FD, FD);

    // 3) eh gather + lc1
    k_zin<<<(NROWS * 16) / 256, 256>>>(p_h, src, dst, p_zin);
    tgemm<0, true, false, false><<<dim3(DG / 64, NROWS / 128), 256, SMG>>>(
        p_zin, whi + OFF_LC1, wlo + OFF_LC1, lc1_b, nullptr, nullptr, p_zg, NROWS, DG, D_EMB);

    // 4) transformer block
    tgemm<0, false, false, false><<<dim3(DG / 64, NROWS / 128), 256, SMG>>>(
        p_zg, whi + OFF_WQ, wlo + OFF_WQ, nullptr, nullptr, nullptr, p_q, NROWS, DG, DG);
    tgemm<0, false, false, false><<<dim3(DG / 64, NROWS / 128), 256, SMG>>>(
        p_zg, whi + OFF_WK, wlo + OFF_WK, nullptr, nullptr, nullptr, p_k, NROWS, DG, DG);
    tgemm<0, false, false, false><<<dim3(DG / 64, NROWS / 128), 256, SMG>>>(
        p_zg, whi + OFF_WV, wlo + OFF_WV, nullptr, nullptr, nullptr, p_v, NROWS, DG, DG);
    k_attn<<<N_EDGES, 256>>>(p_q, p_k, p_v, p_ao);
    tgemm<0, false, true, false><<<dim3(DG / 64, NROWS / 128), 256, SMG>>>(
        p_ao, whi + OFF_WO, wlo + OFF_WO, nullptr, p_zg, nullptr, p_x1, NROWS, DG, DG);
    tgemm<2, false, false, false><<<dim3(4 * DG / 64, NROWS / 128), 256, SMG>>>(
        p_x1, whi + OFF_WF1, wlo + OFF_WF1, nullptr, nullptr, nullptr, p_ffn, NROWS, 4 * DG, DG);
    tgemm<0, false, true, false><<<dim3(DG / 64, NROWS / 128), 256, SMG>>>(
        p_ffn, whi + OFF_WF2, wlo + OFF_WF2, nullptr, p_x1, nullptr, p_x2, NROWS, DG, 4 * DG);

    // 5) lc2
    tgemm<0, true, false, false><<<dim3(1, NROWS / 128), 256, SMG>>>(
        p_x2, whi + OFF_LC2, wlo + OFF_LC2, lc2_b, nullptr, nullptr, p_y, NROWS, D_EMB, DG);

    // 6) lm head GEMM (+partial stats), stats reduce, normalize in place
    lmg<<<dim3(NVT, NROWS / 128), 256, SMG>>>(p_y, whi + OFF_EMB, wlo + OFF_EMB, probs, p_pstat);
    k_red<<<NROWS / 256, 256>>>();
    k_norm<<<NROWS, 256>>>(probs);
}

// round 10
// speedup vs baseline: 2.5328x; 1.0108x over previous
#include <cuda_runtime.h>
#include <cuda_bf16.h>
#include <math.h>
#include <stdint.h>

// ---------------- problem constants ----------------
#define N_NODES 8192
#define N_EDGES 2048
#define L_TOK   8
#define D_EMB   64
#define FD      512
#define DG      256
#define NH      4
#define HD      64
#define VOCAB   10000
#define NROWS   (N_EDGES * L_TOK)   // 16384
#define NVT     157                  // ceil(VOCAB/64)

// ---------------- scratch ----------------
__device__ float g_x  [N_NODES * FD];
__device__ float g_e  [N_EDGES * FD];
__device__ float g_msg[N_EDGES * FD];
__device__ float g_agg[N_NODES * FD];
__device__ float g_h  [N_NODES * FD];
__device__ float g_zin[NROWS * D_EMB];
__device__ float g_zg [NROWS * DG];
__device__ float g_qkv[NROWS * 3 * DG];
__device__ float g_ao [NROWS * DG];
__device__ float g_x1 [NROWS * DG];
__device__ float g_ffn[NROWS * 4 * DG];
__device__ float g_x2 [NROWS * DG];
__device__ float g_y  [NROWS * D_EMB];
__device__ float2 g_pstat[NVT * NROWS];
__device__ float g_Ms[NROWS];
__device__ float g_Is[NROWS];

// pre-split weight planes (packed bf16x2 word = {bf16(2kp), bf16(2kp+1)}, k-major [kp][N]) ----
// lc2_w is (DG=256, 64) -> 128 k-pairs  (R7/R8 bug: was 32*64, corrupting lc2 K>=64)
#define OFF_WMSG  0
#define OFF_WNODE (OFF_WMSG  + 256*512)
#define OFF_LC1   (OFF_WNODE + 256*512)
#define OFF_QKV   (OFF_LC1   + 32*256)
#define OFF_WO    (OFF_QKV   + 128*768)
#define OFF_WF1   (OFF_WO    + 128*256)
#define OFF_WF2   (OFF_WF1   + 128*1024)
#define OFF_LC2   (OFF_WF2   + 512*256)
#define OFF_EMB   (OFF_LC2   + 128*64)
#define TOTAL_PAIRS (OFF_EMB + VOCAB*32)
__device__ uint32_t g_whi[TOTAL_PAIRS];
__device__ uint32_t g_wlo[TOTAL_PAIRS];

// ---------------- helpers ----------------
__device__ __forceinline__ void splitpair(float x0, float x1, uint32_t& hi, uint32_t& lo) {
    __nv_bfloat162 h = __floats2bfloat162_rn(x0, x1);
    float h0 = __bfloat162float(h.x), h1 = __bfloat162float(h.y);
    __nv_bfloat162 l = __floats2bfloat162_rn(x0 - h0, x1 - h1);
    hi = *reinterpret_cast<uint32_t*>(&h);
    lo = *reinterpret_cast<uint32_t*>(&l);
}

__device__ __forceinline__ void mma16(float* c,
    uint32_t a0, uint32_t a1, uint32_t a2, uint32_t a3, uint32_t b0, uint32_t b1)
{
    asm volatile(
        "mma.sync.aligned.m16n8k16.row.col.f32.bf16.bf16.f32 "
        "{%0,%1,%2,%3},{%4,%5,%6,%7},{%8,%9},{%0,%1,%2,%3};"
        : "+f"(c[0]), "+f"(c[1]), "+f"(c[2]), "+f"(c[3])
        : "r"(a0), "r"(a1), "r"(a2), "r"(a3), "r"(b0), "r"(b1));
}

__device__ __forceinline__ float gelu_f(float v) {
    float u = 0.7978845608028654f * (v + 0.044715f * v * v * v);
    float t;
    asm("tanh.approx.f32 %0, %1;" : "=f"(t) : "f"(u));
    return 0.5f * v * (1.f + t);
}

__device__ __forceinline__ void upd_stats(float& m, float& s, float x) {
    if (x > m) { s = s * __expf(m - x) + 1.f; m = x; }
    else       { s += __expf(x - m); }
}

// XOR swizzle: octet lanes get distinct bank columns
__device__ __forceinline__ int swz(int slot, int rc, int DIM) {
    return slot * DIM + (rc ^ ((slot & 3) << 1));
}

// ---------------- small kernels ----------------
__global__ void k_lab_embed_e(const int* __restrict__ etok, const int* __restrict__ maskbits,
                              const float* __restrict__ emb, float* __restrict__ labels_out,
                              float* __restrict__ oute)
{
    int i = blockIdx.x * blockDim.x + threadIdx.x;
    if (i >= NROWS * 16) return;
    int slot = i >> 4, d4 = i & 15;
    int e = slot >> 3;
    int tok = etok[slot];
    bool masked = (maskbits[e] != 0) && (tok > 3);
    int mtok = masked ? 4 : tok;
    if (d4 == 0 && labels_out) labels_out[slot] = masked ? (float)tok : -100.0f;
    ((float4*)oute)[i] = ((const float4*)emb)[mtok * 16 + d4];
}

__global__ void k_embed(const int* __restrict__ toks, const float* __restrict__ emb,
                        float* __restrict__ out, int total_f4)
{
    int i = blockIdx.x * blockDim.x + threadIdx.x;
    if (i >= total_f4) return;
    int slot = i >> 4, d4 = i & 15;
    ((float4*)out)[i] = ((const float4*)emb)[toks[slot] * 16 + d4];
}

__device__ __forceinline__ void prep_k(const float* __restrict__ W, int N, int il, int base) {
    int kp = il / N, n = il - kp * N;
    uint32_t hi, lo;
    splitpair(W[(2 * kp) * N + n], W[(2 * kp + 1) * N + n], hi, lo);
    g_whi[base + il] = hi; g_wlo[base + il] = lo;
}

__global__ void k_prep(const float* __restrict__ Wmsg, const float* __restrict__ Wnode,
                       const float* __restrict__ lc1, const float* __restrict__ Wq,
                       const float* __restrict__ Wk, const float* __restrict__ Wv,
                       const float* __restrict__ Wo, const float* __restrict__ Wf1,
                       const float* __restrict__ Wf2, const float* __restrict__ lc2,
                       const float* __restrict__ emb)
{
    int i = blockIdx.x * blockDim.x + threadIdx.x;
    if (i >= TOTAL_PAIRS) return;
    if      (i < OFF_WNODE) prep_k(Wmsg,  512,  i - OFF_WMSG,  OFF_WMSG);
    else if (i < OFF_LC1)   prep_k(Wnode, 512,  i - OFF_WNODE, OFF_WNODE);
    else if (i < OFF_QKV)   prep_k(lc1,   256,  i - OFF_LC1,   OFF_LC1);
    else if (i < OFF_WO) {
        // merged QKV weight planes: [kp][768], cols 0-255=Wq, 256-511=Wk, 512-767=Wv
        int il = i - OFF_QKV;
        int kp = il / 768, n = il % 768;
        const float* W = (n < 256) ? Wq : (n < 512) ? Wk : Wv;
        int nc = n & 255;
        uint32_t hi, lo;
        splitpair(W[(2 * kp) * 256 + nc], W[(2 * kp + 1) * 256 + nc], hi, lo);
        g_whi[i] = hi; g_wlo[i] = lo;
    }
    else if (i < OFF_WF1)   prep_k(Wo,    256,  i - OFF_WO,    OFF_WO);
    else if (i < OFF_WF2)   prep_k(Wf1,   1024, i - OFF_WF1,   OFF_WF1);
    else if (i < OFF_LC2)   prep_k(Wf2,   256,  i - OFF_WF2,   OFF_WF2);
    else if (i < OFF_EMB)   prep_k(lc2,   64,   i - OFF_LC2,   OFF_LC2);
    else {
        // emb planes k-major: [kp][VOCAB]
        int il = i - OFF_EMB;
        int kp = il / VOCAB, n = il - kp * VOCAB;
        uint32_t hi, lo;
        splitpair(emb[n * 64 + 2 * kp], emb[n * 64 + 2 * kp + 1], hi, lo);
        g_whi[i] = hi; g_wlo[i] = lo;
    }
}

__global__ void k_zero(float* __restrict__ p, int total_f4)
{
    int i = blockIdx.x * blockDim.x + threadIdx.x;
    if (i < total_f4) ((float4*)p)[i] = make_float4(0.f, 0.f, 0.f, 0.f);
}

__global__ void k_scatter(const float* __restrict__ msg, const int* __restrict__ dst,
                          float* __restrict__ agg)
{
    int t = blockIdx.x * blockDim.x + threadIdx.x;
    if (t >= N_EDGES * FD) return;
    int e = t >> 9, c = t & 511;
    atomicAdd(&agg[dst[e] * FD + c], msg[t]);
}

__global__ void k_zin(const float* __restrict__ h, const int* __restrict__ src,
                      const int* __restrict__ dst, float* __restrict__ zin)
{
    int i = blockIdx.x * blockDim.x + threadIdx.x;
    if (i >= NROWS * 16) return;
    int r = i >> 4, d4 = i & 15;
    int e = r >> 3, l = r & 7;
    const float4* h4 = (const float4*)h;
    float4 a = h4[src[e] * 128 + l * 16 + d4];
    float4 b = h4[dst[e] * 128 + l * 16 + d4];
    ((float4*)zin)[i] = make_float4(a.x + b.x, a.y + b.y, a.z + b.z, a.w + b.w);
}

// ---------------- bf16-split tensor GEMM: BM=128, BN=64, BK=32, 2 CTAs/SM ----------------
template<int ACT, bool HAS_BIAS, bool HAS_ADD, bool ADD_IDX>
__global__ void __launch_bounds__(256, 2)
tgemm(const float* __restrict__ A,
      const uint32_t* __restrict__ Bhi, const uint32_t* __restrict__ Blo,
      const float* __restrict__ bias, const float* __restrict__ Add,
      const int* __restrict__ addIdx, float* __restrict__ C,
      int M, int N, int K)
{
    constexpr int BM = 128, BN = 64;
    constexpr int WN = 16, MT = 4, NT = 2;
    constexpr int KC = 8, JP = 4;

    extern __shared__ uint32_t dynsm[];
    uint32_t* AsW[2] = { dynsm, dynsm + BM * 32 };
    uint32_t* BsW[2] = { dynsm + 2 * BM * 32, dynsm + 2 * BM * 32 + BN * 32 };

    int tid = threadIdx.x, lane = tid & 31, w = tid >> 5;
    int g = lane >> 2, tg = lane & 3;
    int wM = w >> 2, wN = w & 3;
    int m0 = blockIdx.y * BM, n0 = blockIdx.x * BN;

    float acc[MT][NT][4];
#pragma unroll
    for (int mt = 0; mt < MT; mt++)
#pragma unroll
        for (int nt = 0; nt < NT; nt++)
#pragma unroll
            for (int c = 0; c < 4; c++) acc[mt][nt][c] = 0.f;

    int arow = tid >> 1, ahalf = tid & 1;
    int bn = tid % BN, bq = tid / BN, kb = bq * KC;

    float sa[16];
    uint32_t hw[JP], lw[JP];

    auto ldA = [&](int k0) {
        const float* p = A + (size_t)(m0 + arow) * K + k0 + ahalf * 16;
#pragma unroll
        for (int j = 0; j < 16; j += 4) *(float4*)&sa[j] = *(const float4*)(p + j);
    };
    auto ldB = [&](int k0) {
        int kp0 = (k0 + kb) >> 1;
#pragma unroll
        for (int jp = 0; jp < JP; jp++) {
            size_t idx = (size_t)(kp0 + jp) * N + n0 + bn;
            hw[jp] = Bhi[idx]; lw[jp] = Blo[idx];
        }
    };
    auto stA = [&](int buf) {
#pragma unroll
        for (int j = 0; j < 16; j += 2) {
            int p = (ahalf * 16 + j) >> 1, s = p >> 3, lp = p & 7, t = lp & 3;
            int off = (lp & 4) ? 2 : 0;
            uint32_t hi, lo; splitpair(sa[j], sa[j + 1], hi, lo);
            *(uint2*)&AsW[buf][swz((s << 2) | t, arow, BM) * 4 + off] = make_uint2(hi, lo);
        }
    };
    auto stB = [&](int buf) {
#pragma unroll
        for (int jp = 0; jp < JP; jp++) {
            int p = (kb >> 1) + jp, s = p >> 3, lp = p & 7, t = lp & 3;
            int off = (lp & 4) ? 2 : 0;
            *(uint2*)&BsW[buf][swz((s << 2) | t, bn, BN) * 4 + off] = make_uint2(hw[jp], lw[jp]);
        }
    };

    int KT = K / 32;
    ldA(0); ldB(0); stA(0); stB(0);
    __syncthreads();
    for (int kt = 0; kt < KT; kt++) {
        int cur = kt & 1;
        if (kt + 1 < KT) { ldA((kt + 1) * 32); ldB((kt + 1) * 32); }
        const uint4* A4 = (const uint4*)AsW[cur];
        const uint4* B4 = (const uint4*)BsW[cur];
#pragma unroll
        for (int s = 0; s < 2; s++) {
            uint4 af[MT][2], bf[NT];
#pragma unroll
            for (int mt = 0; mt < MT; mt++) {
                int mr = wM * 64 + mt * 16 + g;
                af[mt][0] = A4[swz(s * 4 + tg, mr, BM)];
                af[mt][1] = A4[swz(s * 4 + tg, mr + 8, BM)];
            }
#pragma unroll
            for (int nt = 0; nt < NT; nt++)
                bf[nt] = B4[swz(s * 4 + tg, wN * WN + nt * 8 + g, BN)];
#pragma unroll
            for (int mt = 0; mt < MT; mt++)
#pragma unroll
                for (int nt = 0; nt < NT; nt++) {
                    mma16(acc[mt][nt], af[mt][0].x, af[mt][1].x, af[mt][0].z, af[mt][1].z,
                          bf[nt].x, bf[nt].z);
                    mma16(acc[mt][nt], af[mt][0].x, af[mt][1].x, af[mt][0].z, af[mt][1].z,
                          bf[nt].y, bf[nt].w);
                    mma16(acc[mt][nt], af[mt][0].y, af[mt][1].y, af[mt][0].w, af[mt][1].w,
                          bf[nt].x, bf[nt].z);
                }
        }
        if (kt + 1 < KT) { stA((kt + 1) & 1); stB((kt + 1) & 1); }
        __syncthreads();
    }

#pragma unroll
    for (int mt = 0; mt < MT; mt++) {
        int r1 = m0 + wM * 64 + mt * 16 + g;
        int r2 = r1 + 8;
        int a1 = r1, a2 = r2;
        if (HAS_ADD && ADD_IDX) { a1 = addIdx[r1]; a2 = addIdx[r2]; }
#pragma unroll
        for (int nt = 0; nt < NT; nt++) {
            int cb = n0 + wN * WN + nt * 8 + 2 * tg;
            float e0 = acc[mt][nt][0], e1 = acc[mt][nt][1];
            float e2 = acc[mt][nt][2], e3 = acc[mt][nt][3];
            if (HAS_BIAS) { float b0 = bias[cb], b1 = bias[cb + 1]; e0 += b0; e1 += b1; e2 += b0; e3 += b1; }
            if (HAS_ADD) {
                e0 += Add[(size_t)a1 * N + cb]; e1 += Add[(size_t)a1 * N + cb + 1];
                e2 += Add[(size_t)a2 * N + cb]; e3 += Add[(size_t)a2 * N + cb + 1];
            }
            if (ACT == 1) { e0 = fmaxf(e0, 0.f); e1 = fmaxf(e1, 0.f); e2 = fmaxf(e2, 0.f); e3 = fmaxf(e3, 0.f); }
            if (ACT == 2) { e0 = gelu_f(e0); e1 = gelu_f(e1); e2 = gelu_f(e2); e3 = gelu_f(e3); }
            *(float2*)(C + (size_t)r1 * N + cb) = make_float2(e0, e1);
            *(float2*)(C + (size_t)r2 * N + cb) = make_float2(e2, e3);
        }
    }
}

// ---------------- lm_head GEMM + partial softmax stats ----------------
__global__ void __launch_bounds__(256, 2)
lmg(const float* __restrict__ Y,
    const uint32_t* __restrict__ Bhi, const uint32_t* __restrict__ Blo,
    float* __restrict__ logits, float2* __restrict__ pstat)
{
    constexpr int BM = 128, BN = 64;
    constexpr int WN = 16, MT = 4, NT = 2;
    constexpr int KC = 8, JP = 4;
    const int N = VOCAB, K = 64;

    extern __shared__ uint32_t dynsm[];
    uint32_t* AsW[2] = { dynsm, dynsm + BM * 32 };
    uint32_t* BsW[2] = { dynsm + 2 * BM * 32, dynsm + 2 * BM * 32 + BN * 32 };
    __shared__ float2 red[4][BM];

    int tid = threadIdx.x, lane = tid & 31, w = tid >> 5;
    int g = lane >> 2, tg = lane & 3;
    int wM = w >> 2, wN = w & 3;
    int m0 = blockIdx.y * BM, n0 = blockIdx.x * BN;

    float acc[MT][NT][4];
#pragma unroll
    for (int mt = 0; mt < MT; mt++)
#pragma unroll
        for (int nt = 0; nt < NT; nt++)
#pragma unroll
            for (int c = 0; c < 4; c++) acc[mt][nt][c] = 0.f;

    int arow = tid >> 1, ahalf = tid & 1;
    int bn = tid % BN, bq = tid / BN, kb = bq * KC;
    int bcol = n0 + bn;

    float sa[16];
    uint32_t hw[JP], lw[JP];

    auto ldA = [&](int k0) {
        const float* p = Y + (size_t)(m0 + arow) * K + k0 + ahalf * 16;
#pragma unroll
        for (int j = 0; j < 16; j += 4) *(float4*)&sa[j] = *(const float4*)(p + j);
    };
    auto ldB = [&](int k0) {
        int kp0 = (k0 + kb) >> 1;
        if (bcol < N) {
#pragma unroll
            for (int jp = 0; jp < JP; jp++) {
                size_t idx = (size_t)(kp0 + jp) * N + bcol;
                hw[jp] = Bhi[idx]; lw[jp] = Blo[idx];
            }
        } else {
#pragma unroll
            for (int jp = 0; jp < JP; jp++) { hw[jp] = 0; lw[jp] = 0; }
        }
    };
    auto stA = [&](int buf) {
#pragma unroll
        for (int j = 0; j < 16; j += 2) {
            int p = (ahalf * 16 + j) >> 1, s = p >> 3, lp = p & 7, t = lp & 3;
            int off = (lp & 4) ? 2 : 0;
            uint32_t hi, lo; splitpair(sa[j], sa[j + 1], hi, lo);
            *(uint2*)&AsW[buf][swz((s << 2) | t, arow, BM) * 4 + off] = make_uint2(hi, lo);
        }
    };
    auto stB = [&](int buf) {
#pragma unroll
        for (int jp = 0; jp < JP; jp++) {
            int p = (kb >> 1) + jp, s = p >> 3, lp = p & 7, t = lp & 3;
            int off = (lp & 4) ? 2 : 0;
            *(uint2*)&BsW[buf][swz((s << 2) | t, bn, BN) * 4 + off] = make_uint2(hw[jp], lw[jp]);
        }
    };

    ldA(0); ldB(0); stA(0); stB(0);
    __syncthreads();
#pragma unroll
    for (int kt = 0; kt < 2; kt++) {
        int cur = kt & 1;
        if (kt == 0) { ldA(32); ldB(32); }
        const uint4* A4 = (const uint4*)AsW[cur];
        const uint4* B4 = (const uint4*)BsW[cur];
#pragma unroll
        for (int s = 0; s < 2; s++) {
            uint4 af[MT][2], bf[NT];
#pragma unroll
            for (int mt = 0; mt < MT; mt++) {
                int mr = wM * 64 + mt * 16 + g;
                af[mt][0] = A4[swz(s * 4 + tg, mr, BM)];
                af[mt][1] = A4[swz(s * 4 + tg, mr + 8, BM)];
            }
#pragma unroll
            for (int nt = 0; nt < NT; nt++)
                bf[nt] = B4[swz(s * 4 + tg, wN * WN + nt * 8 + g, BN)];
#pragma unroll
            for (int mt = 0; mt < MT; mt++)
#pragma unroll
                for (int nt = 0; nt < NT; nt++) {
                    mma16(acc[mt][nt], af[mt][0].x, af[mt][1].x, af[mt][0].z, af[mt][1].z,
                          bf[nt].x, bf[nt].z);
                    mma16(acc[mt][nt], af[mt][0].x, af[mt][1].x, af[mt][0].z, af[mt][1].z,
                          bf[nt].y, bf[nt].w);
                    mma16(acc[mt][nt], af[mt][0].y, af[mt][1].y, af[mt][0].w, af[mt][1].w,
                          bf[nt].x, bf[nt].z);
                }
        }
        if (kt == 0) { stA(1); stB(1); }
        __syncthreads();
    }

    float mreg[8], sreg[8];
#pragma unroll
    for (int i = 0; i < 8; i++) { mreg[i] = -1e30f; sreg[i] = 0.f; }

#pragma unroll
    for (int mt = 0; mt < MT; mt++) {
        int r1 = m0 + wM * 64 + mt * 16 + g, r2 = r1 + 8;
#pragma unroll
        for (int nt = 0; nt < NT; nt++) {
            int cb = n0 + wN * WN + nt * 8 + 2 * tg;
            if (cb < N) {
                float e0 = acc[mt][nt][0], e1 = acc[mt][nt][1];
                float e2 = acc[mt][nt][2], e3 = acc[mt][nt][3];
                *(float2*)(logits + (size_t)r1 * N + cb) = make_float2(e0, e1);
                *(float2*)(logits + (size_t)r2 * N + cb) = make_float2(e2, e3);
                upd_stats(mreg[mt * 2], sreg[mt * 2], e0);
                upd_stats(mreg[mt * 2], sreg[mt * 2], e1);
                upd_stats(mreg[mt * 2 + 1], sreg[mt * 2 + 1], e2);
                upd_stats(mreg[mt * 2 + 1], sreg[mt * 2 + 1], e3);
            }
        }
    }
#pragma unroll
    for (int i = 0; i < 8; i++) {
#pragma unroll
        for (int d = 1; d < 4; d <<= 1) {
            float om = __shfl_xor_sync(0xffffffffu, mreg[i], d);
            float os = __shfl_xor_sync(0xffffffffu, sreg[i], d);
            float M2 = fmaxf(mreg[i], om);
            sreg[i] = sreg[i] * __expf(mreg[i] - M2) + os * __expf(om - M2);
            mreg[i] = M2;
        }
    }
    if (tg == 0) {
#pragma unroll
        for (int mt = 0; mt < MT; mt++)
#pragma unroll
            for (int h = 0; h < 2; h++)
                red[wN][wM * 64 + mt * 16 + h * 8 + g] =
                    make_float2(mreg[mt * 2 + h], sreg[mt * 2 + h]);
    }
    __syncthreads();
    if (tid < BM) {
        float M2 = -1e30f, S = 0.f;
#pragma unroll
        for (int j = 0; j < 4; j++) {
            float2 r = red[j][tid];
            float nM = fmaxf(M2, r.x);
            S = S * __expf(M2 - nM) + r.y * __expf(r.x - nM);
            M2 = nM;
        }
        pstat[(size_t)blockIdx.x * NROWS + m0 + tid] = make_float2(M2, S);
    }
}

__global__ void k_red()
{
    int r = blockIdx.x * 256 + threadIdx.x;
    if (r >= NROWS) return;
    float M = -1e30f, S = 0.f;
    for (int t = 0; t < NVT; t++) {
        float2 p = g_pstat[(size_t)t * NROWS + r];
        float nM = fmaxf(M, p.x);
        S = S * __expf(M - nM) + p.y * __expf(p.x - nM);
        M = nM;
    }
    g_Ms[r] = M;
    g_Is[r] = 1.f / S;
}

__global__ void __launch_bounds__(256)
k_norm(float* __restrict__ probs)
{
    int row = blockIdx.x, tid = threadIdx.x;
    float M = g_Ms[row], I = g_Is[row];
    float4* p = (float4*)(probs + (size_t)row * VOCAB);
#pragma unroll
    for (int r = 0; r < 10; r++) {
        int i = tid + r * 256;
        if (i < VOCAB / 4) {
            float4 q = p[i];
            q.x = __expf(q.x - M) * I;
            q.y = __expf(q.y - M) * I;
            q.z = __expf(q.z - M) * I;
            q.w = __expf(q.w - M) * I;
            p[i] = q;
        }
    }
}

// ---------------- attention (reads fused qkv [row][768], writes fp32 O) ----------------
__global__ void __launch_bounds__(256)
k_attn(const float* __restrict__ QKV, float* __restrict__ O)
{
    int e = blockIdx.x;
    int tid = threadIdx.x;
    __shared__ float qs[8][DG], ks[8][DG], vs[8][DG];
    __shared__ float att[NH][8][8];

    for (int i = tid; i < 8 * DG; i += 256) {
        int s = i >> 8, c = i & 255;
        size_t base = (size_t)(e * 8 + s) * 768 + c;
        qs[s][c] = QKV[base]; ks[s][c] = QKV[base + 256]; vs[s][c] = QKV[base + 512];
    }
    __syncthreads();
    {
        int h = tid >> 6, rem = tid & 63, qi = rem >> 3, ki = rem & 7;
        float acc = 0.f;
#pragma unroll
        for (int d = 0; d < HD; d++) acc = fmaf(qs[qi][h * HD + d], ks[ki][h * HD + d], acc);
        att[h][qi][ki] = acc * 0.125f;
    }
    __syncthreads();
    if (tid < 32) {
        int h = tid >> 3, qi = tid & 7;
        float m = -1e30f;
#pragma unroll
        for (int ki = 0; ki < 8; ki++) m = fmaxf(m, att[h][qi][ki]);
        float s = 0.f, ex[8];
#pragma unroll
        for (int ki = 0; ki < 8; ki++) { ex[ki] = __expf(att[h][qi][ki] - m); s += ex[ki]; }
        float inv = 1.f / s;
#pragma unroll
        for (int ki = 0; ki < 8; ki++) att[h][qi][ki] = ex[ki] * inv;
    }
    __syncthreads();
    {
        int c = tid, h = c >> 6;
#pragma unroll
        for (int s = 0; s < 8; s++) {
            float acc = 0.f;
#pragma unroll
            for (int ki = 0; ki < 8; ki++) acc = fmaf(att[h][s][ki], vs[ki][c], acc);
            O[(size_t)(e * 8 + s) * DG + c] = acc;
        }
    }
}

// ---------------- host launcher ----------------
extern "C" void kernel_launch(void* const* d_in, const int* in_sizes, int n_in,
                              void* d_out, int out_size)
{
    const int*   node_tokens = (const int*)d_in[0];
    const int*   edge_tokens = (const int*)d_in[1];
    const int*   edge_index  = (const int*)d_in[2];
    const int*   mask_rows   = (const int*)d_in[3];
    const float* emb   = (const float*)d_in[4];
    const float* W_msg = (const float*)d_in[5];
    const float* W_node= (const float*)d_in[6];
    const float* lc1_w = (const float*)d_in[7];
    const float* lc1_b = (const float*)d_in[8];
    const float* lc2_w = (const float*)d_in[9];
    const float* lc2_b = (const float*)d_in[10];
    const float* Wq  = (const float*)d_in[11];
    const float* Wk  = (const float*)d_in[12];
    const float* Wv  = (const float*)d_in[13];
    const float* Wo  = (const float*)d_in[14];
    const float* Wf1 = (const float*)d_in[15];
    const float* Wf2 = (const float*)d_in[16];
    const int* src = edge_index;
    const int* dst = edge_index + N_EDGES;

    float *p_x, *p_e, *p_msg, *p_agg, *p_h, *p_zin, *p_zg, *p_qkv, *p_ao,
          *p_x1, *p_ffn, *p_x2, *p_y;
    float2* p_pstat;
    uint32_t *whi, *wlo;
    cudaGetSymbolAddress((void**)&p_x,   g_x);
    cudaGetSymbolAddress((void**)&p_e,   g_e);
    cudaGetSymbolAddress((void**)&p_msg, g_msg);
    cudaGetSymbolAddress((void**)&p_agg, g_agg);
    cudaGetSymbolAddress((void**)&p_h,   g_h);
    cudaGetSymbolAddress((void**)&p_zin, g_zin);
    cudaGetSymbolAddress((void**)&p_zg,  g_zg);
    cudaGetSymbolAddress((void**)&p_qkv, g_qkv);
    cudaGetSymbolAddress((void**)&p_ao,  g_ao);
    cudaGetSymbolAddress((void**)&p_x1,  g_x1);
    cudaGetSymbolAddress((void**)&p_ffn, g_ffn);
    cudaGetSymbolAddress((void**)&p_x2,  g_x2);
    cudaGetSymbolAddress((void**)&p_y,   g_y);
    cudaGetSymbolAddress((void**)&p_pstat, g_pstat);
    cudaGetSymbolAddress((void**)&whi,   g_whi);
    cudaGetSymbolAddress((void**)&wlo,   g_wlo);

    const int SMG = (2 * 128 * 32 + 2 * 64 * 32) * 4;   // 48KB
    cudaFuncSetAttribute(tgemm<1, false, true, true>,   cudaFuncAttributeMaxDynamicSharedMemorySize, SMG);
    cudaFuncSetAttribute(tgemm<1, false, true, false>,  cudaFuncAttributeMaxDynamicSharedMemorySize, SMG);
    cudaFuncSetAttribute(tgemm<0, true, false, false>,  cudaFuncAttributeMaxDynamicSharedMemorySize, SMG);
    cudaFuncSetAttribute(tgemm<0, false, false, false>, cudaFuncAttributeMaxDynamicSharedMemorySize, SMG);
    cudaFuncSetAttribute(tgemm<0, false, true, false>,  cudaFuncAttributeMaxDynamicSharedMemorySize, SMG);
    cudaFuncSetAttribute(tgemm<2, false, false, false>, cudaFuncAttributeMaxDynamicSharedMemorySize, SMG);
    cudaFuncSetAttribute(lmg, cudaFuncAttributeMaxDynamicSharedMemorySize, SMG);

    // output layout: probs-only, or labels(16384) ++ probs
    float* out = (float*)d_out;
    const long long PROBS_N = (long long)NROWS * VOCAB;
    float* labels_out = nullptr;
    float* probs = out;
    if ((long long)out_size >= PROBS_N + NROWS) { labels_out = out; probs = out + NROWS; }

    // 1) fused labels+edge-embed, node embed, weight presplit
    k_lab_embed_e<<<(NROWS * 16) / 256, 256>>>(edge_tokens, mask_rows, emb, labels_out, p_e);
    k_embed<<<(N_NODES * L_TOK * 16) / 256, 256>>>(node_tokens, emb, p_x, N_NODES * L_TOK * 16);
    k_prep<<<(TOTAL_PAIRS + 255) / 256, 256>>>(W_msg, W_node, lc1_w, Wq, Wk, Wv, Wo, Wf1, Wf2, lc2_w, emb);

    // 2) GNN
    tgemm<1, false, true, true><<<dim3(FD / 64, N_EDGES / 128), 256, SMG>>>(
        p_e, whi + OFF_WMSG, wlo + OFF_WMSG, nullptr, p_x, src, p_msg, N_EDGES, FD, FD);
    k_zero<<<(N_NODES * FD / 4) / 256, 256>>>(p_agg, N_NODES * FD / 4);
    k_scatter<<<(N_EDGES * FD) / 256, 256>>>(p_msg, dst, p_agg);
    tgemm<1, false, true, false><<<dim3(FD / 64, N_NODES / 128), 256, SMG>>>(
        p_x, whi + OFF_WNODE, wlo + OFF_WNODE, nullptr, p_agg, nullptr, p_h, N_NODES, FD, FD);

    // 3) eh gather + lc1
    k_zin<<<(NROWS * 16) / 256, 256>>>(p_h, src, dst, p_zin);
    tgemm<0, true, false, false><<<dim3(DG / 64, NROWS / 128), 256, SMG>>>(
        p_zin, whi + OFF_LC1, wlo + OFF_LC1, lc1_b, nullptr, nullptr, p_zg, NROWS, DG, D_EMB);

    // 4) transformer: fused QKV GEMM, attn, Wo(+res), FFN
    tgemm<0, false, false, false><<<dim3(768 / 64, NROWS / 128), 256, SMG>>>(
        p_zg, whi + OFF_QKV, wlo + OFF_QKV, nullptr, nullptr, nullptr, p_qkv, NROWS, 768, DG);
    k_attn<<<N_EDGES, 256>>>(p_qkv, p_ao);
    tgemm<0, false, true, false><<<dim3(DG / 64, NROWS / 128), 256, SMG>>>(
        p_ao, whi + OFF_WO, wlo + OFF_WO, nullptr, p_zg, nullptr, p_x1, NROWS, DG, DG);
    tgemm<2, false, false, false><<<dim3(4 * DG / 64, NROWS / 128), 256, SMG>>>(
        p_x1, whi + OFF_WF1, wlo + OFF_WF1, nullptr, nullptr, nullptr, p_ffn, NROWS, 4 * DG, DG);
    tgemm<0, false, true, false><<<dim3(DG / 64, NROWS / 128), 256, SMG>>>(
        p_ffn, whi + OFF_WF2, wlo + OFF_WF2, nullptr, p_x1, nullptr, p_x2, NROWS, DG, 4 * DG);

    // 5) lc2
    tgemm<0, true, false, false><<<dim3(1, NROWS / 128), 256, SMG>>>(
        p_x2, whi + OFF_LC2, wlo + OFF_LC2, lc2_b, nullptr, nullptr, p_y, NROWS, D_EMB, DG);

    // 6) lm head GEMM (+partial stats), stats reduce, normalize in place
    lmg<<<dim3(NVT, NROWS / 128), 256, SMG>>>(p_y, whi + OFF_EMB, wlo + OFF_EMB, probs, p_pstat);
    k_red<<<NROWS / 256, 256>>>();
    k_norm<<<NROWS, 256>>>(probs);
}